// round 2
// baseline (speedup 1.0000x reference)
#include <cuda_runtime.h>
#include <cstdint>

// Problem constants (fixed by the reference)
#define NN    20000
#define DIN   128
#define HH    4
#define C1V   256
#define HIDV  1024
#define COUTV 512
#define EE    160000
#define ETOT  (EE + NN)

// ---------------------------------------------------------------------------
// Scratch (device globals: allocation-free per harness rules)
// ---------------------------------------------------------------------------
__device__ float d_xw [NN * HIDV];   // GEMM output / attention features
__device__ float d_agg[NN * HIDV];   // aggregated messages (pre-LN)
__device__ float d_hb [NN * HIDV];   // post LN+ELU activations
__device__ float d_es [NN * HH];
__device__ float d_ed [NN * HH];
__device__ int   d_cnt[NN];
__device__ int   d_off[NN + 1];
__device__ int   d_cur[NN];
__device__ int   d_csr[ETOT];
__device__ int   d_is64;             // edge_index dtype flag (1 = int64)

// ---------------------------------------------------------------------------
// edge_index dtype detection: int64 values < 20000 have zero odd 32-bit words
// ---------------------------------------------------------------------------
__global__ void detect_dtype(const int* __restrict__ ei32) {
    int all_zero = 1;
    #pragma unroll
    for (int i = 1; i < 64; i += 2)
        if (ei32[i] != 0) all_zero = 0;
    d_is64 = all_zero;
}

__device__ __forceinline__ int edge_at(const void* ei, long long idx) {
    if (d_is64) return (int)((const long long*)ei)[idx];
    return ((const int*)ei)[idx];
}

// ---------------------------------------------------------------------------
// CSR-by-dst construction (counting sort)
// ---------------------------------------------------------------------------
__global__ void count_edges(const void* __restrict__ ei, int* __restrict__ cnt) {
    int e = blockIdx.x * blockDim.x + threadIdx.x;
    if (e >= ETOT) return;
    int d = (e < EE) ? edge_at(ei, (long long)EE + e) : (e - EE);
    atomicAdd(&cnt[d], 1);
}

__global__ void scan_offsets(const int* __restrict__ cnt, int* __restrict__ off,
                             int* __restrict__ cur, int n) {
    __shared__ int sh[1024];
    int carry = 0;
    for (int base = 0; base < n; base += 1024) {
        int i = base + threadIdx.x;
        int v = (i < n) ? cnt[i] : 0;
        sh[threadIdx.x] = v;
        __syncthreads();
        for (int o = 1; o < 1024; o <<= 1) {
            int t = (threadIdx.x >= o) ? sh[threadIdx.x - o] : 0;
            __syncthreads();
            sh[threadIdx.x] += t;
            __syncthreads();
        }
        if (i < n) { int ex = carry + sh[threadIdx.x] - v; off[i] = ex; cur[i] = ex; }
        carry += sh[1023];
        __syncthreads();
    }
    if (threadIdx.x == 0) off[n] = carry;
}

__global__ void scatter_edges(const void* __restrict__ ei,
                              int* __restrict__ cur, int* __restrict__ csr) {
    int e = blockIdx.x * blockDim.x + threadIdx.x;
    if (e >= ETOT) return;
    int s = (e < EE) ? edge_at(ei, e)                  : (e - EE);
    int d = (e < EE) ? edge_at(ei, (long long)EE + e)  : (e - EE);
    int pos = atomicAdd(&cur[d], 1);
    csr[pos] = s;
}

// ---------------------------------------------------------------------------
// SGEMM: C[M,N] = A[M,K] @ B[K,N], fp32, 64x64 block tile, 4x4 micro tile
// ---------------------------------------------------------------------------
__global__ __launch_bounds__(256) void sgemm64(const float* __restrict__ A,
                                               const float* __restrict__ B,
                                               float* __restrict__ C,
                                               int M, int N, int K) {
    __shared__ float As[16][64];
    __shared__ float Bs[16][64];
    int tid = threadIdx.x;
    int tx = tid & 15, ty = tid >> 4;
    int m0 = blockIdx.x * 64, n0 = blockIdx.y * 64;
    float acc[4][4] = {};
    for (int k0 = 0; k0 < K; k0 += 16) {
        #pragma unroll
        for (int l = tid; l < 1024; l += 256) {
            int m = l >> 4, kk = l & 15;
            int gm = m0 + m;
            As[kk][m] = (gm < M) ? A[(size_t)gm * K + k0 + kk] : 0.f;
        }
        #pragma unroll
        for (int l = tid; l < 1024; l += 256) {
            int kk = l >> 6, nn = l & 63;
            Bs[kk][nn] = B[(size_t)(k0 + kk) * N + n0 + nn];
        }
        __syncthreads();
        #pragma unroll
        for (int kk = 0; kk < 16; kk++) {
            float a[4], b[4];
            #pragma unroll
            for (int i = 0; i < 4; i++) a[i] = As[kk][ty * 4 + i];
            #pragma unroll
            for (int j = 0; j < 4; j++) b[j] = Bs[kk][tx * 4 + j];
            #pragma unroll
            for (int i = 0; i < 4; i++)
                #pragma unroll
                for (int j = 0; j < 4; j++)
                    acc[i][j] = fmaf(a[i], b[j], acc[i][j]);
        }
        __syncthreads();
    }
    #pragma unroll
    for (int i = 0; i < 4; i++) {
        int gm = m0 + ty * 4 + i;
        if (gm < M) {
            #pragma unroll
            for (int j = 0; j < 4; j++)
                C[(size_t)gm * N + n0 + tx * 4 + j] = acc[i][j];
        }
    }
}

// ---------------------------------------------------------------------------
// Per-node attention scores: es[n,h] = <xw[n,h,:], a_src[h,:]>, ed likewise
// ---------------------------------------------------------------------------
template<int H, int C>
__global__ void attn_scores(const float* __restrict__ xw,
                            const float* __restrict__ asrc,
                            const float* __restrict__ adst,
                            float* __restrict__ es, float* __restrict__ ed) {
    int n = blockIdx.x;
    int w = threadIdx.x >> 5, lane = threadIdx.x & 31;
    const float* row = xw + (size_t)n * H * C + w * C;
    float ss = 0.f, sd = 0.f;
    for (int c = lane; c < C; c += 32) {
        float v = row[c];
        ss += v * asrc[w * C + c];
        sd += v * adst[w * C + c];
    }
    #pragma unroll
    for (int o = 16; o; o >>= 1) {
        ss += __shfl_down_sync(0xffffffffu, ss, o);
        sd += __shfl_down_sync(0xffffffffu, sd, o);
    }
    if (!lane) { es[n * H + w] = ss; ed[n * H + w] = sd; }
}

// ---------------------------------------------------------------------------
// GAT aggregation: one block per dst node, segment softmax + weighted gather.
// ---------------------------------------------------------------------------
template<int H, int C>
__global__ __launch_bounds__(256) void gat_aggregate(
        const float* __restrict__ xw, const float* __restrict__ es,
        const float* __restrict__ ed, const int* __restrict__ off,
        const int* __restrict__ csr, const float* __restrict__ bias,
        float* __restrict__ out) {
    constexpr int HC = H * C;
    constexpr int F  = HC / 256;
    int n = blockIdx.x, tid = threadIdx.x;
    __shared__ float ed_sh[H], mx_sh[H], id_sh[H], red[256];
    __shared__ float alpha_sh[64 * H];
    __shared__ int   src_sh[64];
    if (tid < H) ed_sh[tid] = ed[n * H + tid];
    __syncthreads();
    int start = off[n];
    int deg   = off[n + 1] - start;   // >= 1 always (self loop)

    // Phase A: max per head
    float lmax[H];
    #pragma unroll
    for (int h = 0; h < H; h++) lmax[h] = -3.4e38f;
    for (int i = tid; i < deg; i += 256) {
        int s = csr[start + i];
        #pragma unroll
        for (int h = 0; h < H; h++) {
            float e = es[s * H + h] + ed_sh[h];
            e = (e > 0.f) ? e : 0.2f * e;
            lmax[h] = fmaxf(lmax[h], e);
        }
    }
    #pragma unroll
    for (int h = 0; h < H; h++) {
        red[tid] = lmax[h]; __syncthreads();
        for (int o = 128; o; o >>= 1) {
            if (tid < o) red[tid] = fmaxf(red[tid], red[tid + o]);
            __syncthreads();
        }
        if (!tid) mx_sh[h] = red[0];
        __syncthreads();
    }

    // Phase B: denominator per head
    float lsum[H];
    #pragma unroll
    for (int h = 0; h < H; h++) lsum[h] = 0.f;
    for (int i = tid; i < deg; i += 256) {
        int s = csr[start + i];
        #pragma unroll
        for (int h = 0; h < H; h++) {
            float e = es[s * H + h] + ed_sh[h];
            e = (e > 0.f) ? e : 0.2f * e;
            lsum[h] += expf(e - mx_sh[h]);
        }
    }
    #pragma unroll
    for (int h = 0; h < H; h++) {
        red[tid] = lsum[h]; __syncthreads();
        for (int o = 128; o; o >>= 1) {
            if (tid < o) red[tid] += red[tid + o];
            __syncthreads();
        }
        if (!tid) id_sh[h] = 1.f / (red[0] + 1e-16f);
        __syncthreads();
    }

    // Phase C: weighted feature accumulation, chunks of 64 edges
    float acc[F];
    #pragma unroll
    for (int k = 0; k < F; k++) acc[k] = 0.f;
    const int head = (tid * F) / C;
    for (int c0 = 0; c0 < deg; c0 += 64) {
        int nc = min(64, deg - c0);
        if (tid < nc * H) {
            int j = tid / H, h = tid - j * H;
            int s = csr[start + c0 + j];
            if (h == 0) src_sh[j] = s;
            float e = es[s * H + h] + ed_sh[h];
            e = (e > 0.f) ? e : 0.2f * e;
            alpha_sh[j * H + h] = expf(e - mx_sh[h]) * id_sh[h];
        }
        __syncthreads();
        for (int j = 0; j < nc; j++) {
            int s = src_sh[j];
            float a = alpha_sh[j * H + head];
            const float* row = xw + (size_t)s * HC + tid * F;
            if constexpr (F == 4) {
                float4 v = *reinterpret_cast<const float4*>(row);
                acc[0] = fmaf(a, v.x, acc[0]); acc[1] = fmaf(a, v.y, acc[1]);
                acc[2] = fmaf(a, v.z, acc[2]); acc[3] = fmaf(a, v.w, acc[3]);
            } else {
                float2 v = *reinterpret_cast<const float2*>(row);
                acc[0] = fmaf(a, v.x, acc[0]); acc[1] = fmaf(a, v.y, acc[1]);
            }
        }
        __syncthreads();
    }
    float* o = out + (size_t)n * HC + tid * F;
    #pragma unroll
    for (int k = 0; k < F; k++) o[k] = acc[k] + bias[tid * F + k];
}

// ---------------------------------------------------------------------------
// Fused LayerNorm + ELU over rows of width 1024 (input already has GAT bias)
// ---------------------------------------------------------------------------
__global__ __launch_bounds__(256) void ln_elu(const float* __restrict__ in,
                                              const float* __restrict__ g,
                                              const float* __restrict__ b,
                                              float* __restrict__ out) {
    int n = blockIdx.x, tid = threadIdx.x;
    const float4 v = *reinterpret_cast<const float4*>(in + (size_t)n * 1024 + tid * 4);
    float s  = v.x + v.y + v.z + v.w;
    float sq = v.x * v.x + v.y * v.y + v.z * v.z + v.w * v.w;
    __shared__ float r1[256], r2[256];
    r1[tid] = s; r2[tid] = sq; __syncthreads();
    for (int o = 128; o; o >>= 1) {
        if (tid < o) { r1[tid] += r1[tid + o]; r2[tid] += r2[tid + o]; }
        __syncthreads();
    }
    float mean = r1[0] * (1.f / 1024.f);
    float var  = r2[0] * (1.f / 1024.f) - mean * mean;
    float rstd = rsqrtf(var + 1e-5f);
    const float4 gv = *reinterpret_cast<const float4*>(g + tid * 4);
    const float4 bv = *reinterpret_cast<const float4*>(b + tid * 4);
    float xin[4] = {v.x, v.y, v.z, v.w};
    float gg[4]  = {gv.x, gv.y, gv.z, gv.w};
    float bb[4]  = {bv.x, bv.y, bv.z, bv.w};
    float4 r;
    float* rp = &r.x;
    #pragma unroll
    for (int k = 0; k < 4; k++) {
        float y = (xin[k] - mean) * rstd * gg[k] + bb[k];
        rp[k] = (y > 0.f) ? y : expm1f(y);
    }
    *reinterpret_cast<float4*>(out + (size_t)n * 1024 + tid * 4) = r;
}

// ---------------------------------------------------------------------------
// Launch
// ---------------------------------------------------------------------------
extern "C" void kernel_launch(void* const* d_in, const int* in_sizes, int n_in,
                              void* d_out, int out_size) {
    const float* x   = (const float*)d_in[0];
    const void*  ei  = d_in[1];                 // int32 or int64 (detected)
    const float* W1  = (const float*)d_in[2];
    const float* as1 = (const float*)d_in[3];
    const float* ad1 = (const float*)d_in[4];
    const float* b1  = (const float*)d_in[5];
    const float* g1  = (const float*)d_in[6];
    const float* bt1 = (const float*)d_in[7];
    const float* W2  = (const float*)d_in[8];
    const float* as2 = (const float*)d_in[9];
    const float* ad2 = (const float*)d_in[10];
    const float* b2  = (const float*)d_in[11];
    const float* g2  = (const float*)d_in[12];
    const float* bt2 = (const float*)d_in[13];
    const float* W3  = (const float*)d_in[14];
    const float* as3 = (const float*)d_in[15];
    const float* ad3 = (const float*)d_in[16];
    const float* b3  = (const float*)d_in[17];
    float* out = (float*)d_out;

    float *xw, *agg, *hb, *es, *ed;
    int *cnt, *off, *cur, *csr;
    cudaGetSymbolAddress((void**)&xw,  d_xw);
    cudaGetSymbolAddress((void**)&agg, d_agg);
    cudaGetSymbolAddress((void**)&hb,  d_hb);
    cudaGetSymbolAddress((void**)&es,  d_es);
    cudaGetSymbolAddress((void**)&ed,  d_ed);
    cudaGetSymbolAddress((void**)&cnt, d_cnt);
    cudaGetSymbolAddress((void**)&off, d_off);
    cudaGetSymbolAddress((void**)&cur, d_cur);
    cudaGetSymbolAddress((void**)&csr, d_csr);

    // Detect edge_index dtype, then build CSR by destination (counting sort)
    detect_dtype<<<1, 1>>>((const int*)ei);
    cudaMemsetAsync(cnt, 0, NN * sizeof(int));
    count_edges<<<(ETOT + 255) / 256, 256>>>(ei, cnt);
    scan_offsets<<<1, 1024>>>(cnt, off, cur, NN);
    scatter_edges<<<(ETOT + 255) / 256, 256>>>(ei, cur, csr);

    // ---- Layer 1 ----
    sgemm64<<<dim3((NN + 63) / 64, HIDV / 64), 256>>>(x, W1, xw, NN, HIDV, DIN);
    attn_scores<HH, C1V><<<NN, 32 * HH>>>(xw, as1, ad1, es, ed);
    gat_aggregate<HH, C1V><<<NN, 256>>>(xw, es, ed, off, csr, b1, agg);
    ln_elu<<<NN, 256>>>(agg, g1, bt1, hb);

    // ---- Layer 2 ----
    sgemm64<<<dim3((NN + 63) / 64, HIDV / 64), 256>>>(hb, W2, xw, NN, HIDV, HIDV);
    attn_scores<HH, C1V><<<NN, 32 * HH>>>(xw, as2, ad2, es, ed);
    gat_aggregate<HH, C1V><<<NN, 256>>>(xw, es, ed, off, csr, b2, agg);
    ln_elu<<<NN, 256>>>(agg, g2, bt2, hb);

    // ---- Layer 3 ----
    sgemm64<<<dim3((NN + 63) / 64, COUTV / 64), 256>>>(hb, W3, xw, NN, COUTV, HIDV);
    attn_scores<1, COUTV><<<NN, 32>>>(xw, as3, ad3, es, ed);
    gat_aggregate<1, COUTV><<<NN, 256>>>(xw, es, ed, off, csr, b3, out);
}

// round 3
// speedup vs baseline: 1.2138x; 1.2138x over previous
#include <cuda_runtime.h>
#include <cstdint>

// Problem constants (fixed by the reference)
#define NN    20000
#define DIN   128
#define HH    4
#define C1V   256
#define HIDV  1024
#define COUTV 512
#define EE    160000
#define ETOT  (EE + NN)

// ---------------------------------------------------------------------------
// Scratch (device globals: allocation-free per harness rules)
// ---------------------------------------------------------------------------
__device__ float d_xw [NN * HIDV];   // GEMM output / attention features
__device__ float d_agg[NN * HIDV];   // aggregated messages (pre-LN)
__device__ float d_hb [NN * HIDV];   // post LN+ELU activations
__device__ float d_es [NN * HH];
__device__ float d_ed [NN * HH];
__device__ int   d_cnt[NN];
__device__ int   d_off[NN + 1];
__device__ int   d_cur[NN];
__device__ int   d_csr[ETOT];
__device__ int   d_is64;             // edge_index dtype flag (1 = int64)

// ---------------------------------------------------------------------------
// edge_index dtype detection: int64 values < 20000 have zero odd 32-bit words
// ---------------------------------------------------------------------------
__global__ void detect_dtype(const int* __restrict__ ei32) {
    int all_zero = 1;
    #pragma unroll
    for (int i = 1; i < 64; i += 2)
        if (ei32[i] != 0) all_zero = 0;
    d_is64 = all_zero;
}

__device__ __forceinline__ int edge_at(const void* ei, long long idx) {
    if (d_is64) return (int)((const long long*)ei)[idx];
    return ((const int*)ei)[idx];
}

// ---------------------------------------------------------------------------
// CSR-by-dst construction (counting sort)
// ---------------------------------------------------------------------------
__global__ void count_edges(const void* __restrict__ ei, int* __restrict__ cnt) {
    int e = blockIdx.x * blockDim.x + threadIdx.x;
    if (e >= ETOT) return;
    int d = (e < EE) ? edge_at(ei, (long long)EE + e) : (e - EE);
    atomicAdd(&cnt[d], 1);
}

__global__ void scan_offsets(const int* __restrict__ cnt, int* __restrict__ off,
                             int* __restrict__ cur, int n) {
    __shared__ int sh[1024];
    int carry = 0;
    for (int base = 0; base < n; base += 1024) {
        int i = base + threadIdx.x;
        int v = (i < n) ? cnt[i] : 0;
        sh[threadIdx.x] = v;
        __syncthreads();
        for (int o = 1; o < 1024; o <<= 1) {
            int t = (threadIdx.x >= o) ? sh[threadIdx.x - o] : 0;
            __syncthreads();
            sh[threadIdx.x] += t;
            __syncthreads();
        }
        if (i < n) { int ex = carry + sh[threadIdx.x] - v; off[i] = ex; cur[i] = ex; }
        carry += sh[1023];
        __syncthreads();
    }
    if (threadIdx.x == 0) off[n] = carry;
}

__global__ void scatter_edges(const void* __restrict__ ei,
                              int* __restrict__ cur, int* __restrict__ csr) {
    int e = blockIdx.x * blockDim.x + threadIdx.x;
    if (e >= ETOT) return;
    int s = (e < EE) ? edge_at(ei, e)                  : (e - EE);
    int d = (e < EE) ? edge_at(ei, (long long)EE + e)  : (e - EE);
    int pos = atomicAdd(&cur[d], 1);
    csr[pos] = s;
}

// ---------------------------------------------------------------------------
// SGEMM: C[M,N] = A[M,K] @ B[K,N], fp32.
// 128x128 block tile, 8x8 micro tile (split 4+4), double-buffered smem,
// float4 global loads. Requires K%16==0, N%128==0. M guarded.
// ---------------------------------------------------------------------------
__global__ __launch_bounds__(256) void sgemm128(const float* __restrict__ A,
                                                const float* __restrict__ B,
                                                float* __restrict__ C,
                                                int M, int N, int K) {
    __shared__ float As[2][16][128];
    __shared__ float Bs[2][16][128];
    const int tid = threadIdx.x;
    const int tx = tid & 15, ty = tid >> 4;
    const int m0 = blockIdx.x * 128, n0 = blockIdx.y * 128;

    // A-tile loader coords: 512 float4 per 128x16 tile; this thread does 2.
    const int ar0 = tid >> 2;                 // row within tile (0..63)
    const int ar1 = ar0 + 64;                 // second row (64..127)
    const int ak  = (tid & 3) * 4;            // k offset (0,4,8,12)
    // B-tile loader coords: 16x128 tile, 512 float4; this thread does 2.
    const int bk0 = tid >> 5;                 // k row (0..7)
    const int bk1 = bk0 + 8;                  // k row (8..15)
    const int bn  = (tid & 31) * 4;           // n offset

    const int gm_a0 = m0 + ar0, gm_a1 = m0 + ar1;
    const int nt = K / 16;

    float4 av0, av1, bv0, bv1;
    const float4 z4 = make_float4(0.f, 0.f, 0.f, 0.f);

    // Prefetch tile 0
    av0 = (gm_a0 < M) ? *(const float4*)&A[(size_t)gm_a0 * K + ak] : z4;
    av1 = (gm_a1 < M) ? *(const float4*)&A[(size_t)gm_a1 * K + ak] : z4;
    bv0 = *(const float4*)&B[(size_t)bk0 * N + n0 + bn];
    bv1 = *(const float4*)&B[(size_t)bk1 * N + n0 + bn];
    As[0][ak + 0][ar0] = av0.x; As[0][ak + 1][ar0] = av0.y;
    As[0][ak + 2][ar0] = av0.z; As[0][ak + 3][ar0] = av0.w;
    As[0][ak + 0][ar1] = av1.x; As[0][ak + 1][ar1] = av1.y;
    As[0][ak + 2][ar1] = av1.z; As[0][ak + 3][ar1] = av1.w;
    *(float4*)&Bs[0][bk0][bn] = bv0;
    *(float4*)&Bs[0][bk1][bn] = bv1;
    __syncthreads();

    float acc[8][8] = {};
    int buf = 0;
    for (int kt = 0; kt < nt; kt++) {
        // Issue next-tile global loads into registers (overlap with compute)
        if (kt + 1 < nt) {
            int k0 = (kt + 1) * 16;
            av0 = (gm_a0 < M) ? *(const float4*)&A[(size_t)gm_a0 * K + k0 + ak] : z4;
            av1 = (gm_a1 < M) ? *(const float4*)&A[(size_t)gm_a1 * K + k0 + ak] : z4;
            bv0 = *(const float4*)&B[(size_t)(k0 + bk0) * N + n0 + bn];
            bv1 = *(const float4*)&B[(size_t)(k0 + bk1) * N + n0 + bn];
        }
        #pragma unroll
        for (int kk = 0; kk < 16; kk++) {
            float4 a0 = *(const float4*)&As[buf][kk][ty * 4];
            float4 a1 = *(const float4*)&As[buf][kk][64 + ty * 4];
            float4 b0 = *(const float4*)&Bs[buf][kk][tx * 4];
            float4 b1 = *(const float4*)&Bs[buf][kk][64 + tx * 4];
            float a[8] = {a0.x, a0.y, a0.z, a0.w, a1.x, a1.y, a1.z, a1.w};
            float b[8] = {b0.x, b0.y, b0.z, b0.w, b1.x, b1.y, b1.z, b1.w};
            #pragma unroll
            for (int i = 0; i < 8; i++)
                #pragma unroll
                for (int j = 0; j < 8; j++)
                    acc[i][j] = fmaf(a[i], b[j], acc[i][j]);
        }
        if (kt + 1 < nt) {
            int nb = buf ^ 1;
            As[nb][ak + 0][ar0] = av0.x; As[nb][ak + 1][ar0] = av0.y;
            As[nb][ak + 2][ar0] = av0.z; As[nb][ak + 3][ar0] = av0.w;
            As[nb][ak + 0][ar1] = av1.x; As[nb][ak + 1][ar1] = av1.y;
            As[nb][ak + 2][ar1] = av1.z; As[nb][ak + 3][ar1] = av1.w;
            *(float4*)&Bs[nb][bk0][bn] = bv0;
            *(float4*)&Bs[nb][bk1][bn] = bv1;
        }
        __syncthreads();
        buf ^= 1;
    }

    // Epilogue: 8 rows x (4+4) cols, vectorized stores
    #pragma unroll
    for (int i = 0; i < 8; i++) {
        int lr = (i < 4) ? (ty * 4 + i) : (64 + ty * 4 + i - 4);
        int gm = m0 + lr;
        if (gm < M) {
            float4 c0 = make_float4(acc[i][0], acc[i][1], acc[i][2], acc[i][3]);
            float4 c1 = make_float4(acc[i][4], acc[i][5], acc[i][6], acc[i][7]);
            *(float4*)&C[(size_t)gm * N + n0 + tx * 4]      = c0;
            *(float4*)&C[(size_t)gm * N + n0 + 64 + tx * 4] = c1;
        }
    }
}

// ---------------------------------------------------------------------------
// Per-node attention scores: es[n,h] = <xw[n,h,:], a_src[h,:]>, ed likewise
// ---------------------------------------------------------------------------
template<int H, int C>
__global__ void attn_scores(const float* __restrict__ xw,
                            const float* __restrict__ asrc,
                            const float* __restrict__ adst,
                            float* __restrict__ es, float* __restrict__ ed) {
    int n = blockIdx.x;
    int w = threadIdx.x >> 5, lane = threadIdx.x & 31;
    const float* row = xw + (size_t)n * H * C + w * C;
    float ss = 0.f, sd = 0.f;
    for (int c = lane; c < C; c += 32) {
        float v = row[c];
        ss += v * asrc[w * C + c];
        sd += v * adst[w * C + c];
    }
    #pragma unroll
    for (int o = 16; o; o >>= 1) {
        ss += __shfl_down_sync(0xffffffffu, ss, o);
        sd += __shfl_down_sync(0xffffffffu, sd, o);
    }
    if (!lane) { es[n * H + w] = ss; ed[n * H + w] = sd; }
}

// ---------------------------------------------------------------------------
// GAT aggregation: one block per dst node, segment softmax + weighted gather.
// ---------------------------------------------------------------------------
template<int H, int C>
__global__ __launch_bounds__(256) void gat_aggregate(
        const float* __restrict__ xw, const float* __restrict__ es,
        const float* __restrict__ ed, const int* __restrict__ off,
        const int* __restrict__ csr, const float* __restrict__ bias,
        float* __restrict__ out) {
    constexpr int HC = H * C;
    constexpr int F  = HC / 256;
    int n = blockIdx.x, tid = threadIdx.x;
    __shared__ float ed_sh[H], mx_sh[H], id_sh[H], red[256];
    __shared__ float alpha_sh[64 * H];
    __shared__ int   src_sh[64];
    if (tid < H) ed_sh[tid] = ed[n * H + tid];
    __syncthreads();
    int start = off[n];
    int deg   = off[n + 1] - start;   // >= 1 always (self loop)

    // Phase A: max per head
    float lmax[H];
    #pragma unroll
    for (int h = 0; h < H; h++) lmax[h] = -3.4e38f;
    for (int i = tid; i < deg; i += 256) {
        int s = csr[start + i];
        #pragma unroll
        for (int h = 0; h < H; h++) {
            float e = es[s * H + h] + ed_sh[h];
            e = (e > 0.f) ? e : 0.2f * e;
            lmax[h] = fmaxf(lmax[h], e);
        }
    }
    #pragma unroll
    for (int h = 0; h < H; h++) {
        red[tid] = lmax[h]; __syncthreads();
        for (int o = 128; o; o >>= 1) {
            if (tid < o) red[tid] = fmaxf(red[tid], red[tid + o]);
            __syncthreads();
        }
        if (!tid) mx_sh[h] = red[0];
        __syncthreads();
    }

    // Phase B: denominator per head
    float lsum[H];
    #pragma unroll
    for (int h = 0; h < H; h++) lsum[h] = 0.f;
    for (int i = tid; i < deg; i += 256) {
        int s = csr[start + i];
        #pragma unroll
        for (int h = 0; h < H; h++) {
            float e = es[s * H + h] + ed_sh[h];
            e = (e > 0.f) ? e : 0.2f * e;
            lsum[h] += expf(e - mx_sh[h]);
        }
    }
    #pragma unroll
    for (int h = 0; h < H; h++) {
        red[tid] = lsum[h]; __syncthreads();
        for (int o = 128; o; o >>= 1) {
            if (tid < o) red[tid] += red[tid + o];
            __syncthreads();
        }
        if (!tid) id_sh[h] = 1.f / (red[0] + 1e-16f);
        __syncthreads();
    }

    // Phase C: weighted feature accumulation, chunks of 64 edges
    float acc[F];
    #pragma unroll
    for (int k = 0; k < F; k++) acc[k] = 0.f;
    const int head = (tid * F) / C;
    for (int c0 = 0; c0 < deg; c0 += 64) {
        int nc = min(64, deg - c0);
        if (tid < nc * H) {
            int j = tid / H, h = tid - j * H;
            int s = csr[start + c0 + j];
            if (h == 0) src_sh[j] = s;
            float e = es[s * H + h] + ed_sh[h];
            e = (e > 0.f) ? e : 0.2f * e;
            alpha_sh[j * H + h] = expf(e - mx_sh[h]) * id_sh[h];
        }
        __syncthreads();
        for (int j = 0; j < nc; j++) {
            int s = src_sh[j];
            float a = alpha_sh[j * H + head];
            const float* row = xw + (size_t)s * HC + tid * F;
            if constexpr (F == 4) {
                float4 v = *reinterpret_cast<const float4*>(row);
                acc[0] = fmaf(a, v.x, acc[0]); acc[1] = fmaf(a, v.y, acc[1]);
                acc[2] = fmaf(a, v.z, acc[2]); acc[3] = fmaf(a, v.w, acc[3]);
            } else {
                float2 v = *reinterpret_cast<const float2*>(row);
                acc[0] = fmaf(a, v.x, acc[0]); acc[1] = fmaf(a, v.y, acc[1]);
            }
        }
        __syncthreads();
    }
    float* o = out + (size_t)n * HC + tid * F;
    #pragma unroll
    for (int k = 0; k < F; k++) o[k] = acc[k] + bias[tid * F + k];
}

// ---------------------------------------------------------------------------
// Fused LayerNorm + ELU over rows of width 1024 (input already has GAT bias)
// ---------------------------------------------------------------------------
__global__ __launch_bounds__(256) void ln_elu(const float* __restrict__ in,
                                              const float* __restrict__ g,
                                              const float* __restrict__ b,
                                              float* __restrict__ out) {
    int n = blockIdx.x, tid = threadIdx.x;
    const float4 v = *reinterpret_cast<const float4*>(in + (size_t)n * 1024 + tid * 4);
    float s  = v.x + v.y + v.z + v.w;
    float sq = v.x * v.x + v.y * v.y + v.z * v.z + v.w * v.w;
    __shared__ float r1[256], r2[256];
    r1[tid] = s; r2[tid] = sq; __syncthreads();
    for (int o = 128; o; o >>= 1) {
        if (tid < o) { r1[tid] += r1[tid + o]; r2[tid] += r2[tid + o]; }
        __syncthreads();
    }
    float mean = r1[0] * (1.f / 1024.f);
    float var  = r2[0] * (1.f / 1024.f) - mean * mean;
    float rstd = rsqrtf(var + 1e-5f);
    const float4 gv = *reinterpret_cast<const float4*>(g + tid * 4);
    const float4 bv = *reinterpret_cast<const float4*>(b + tid * 4);
    float xin[4] = {v.x, v.y, v.z, v.w};
    float gg[4]  = {gv.x, gv.y, gv.z, gv.w};
    float bb[4]  = {bv.x, bv.y, bv.z, bv.w};
    float4 r;
    float* rp = &r.x;
    #pragma unroll
    for (int k = 0; k < 4; k++) {
        float y = (xin[k] - mean) * rstd * gg[k] + bb[k];
        rp[k] = (y > 0.f) ? y : expm1f(y);
    }
    *reinterpret_cast<float4*>(out + (size_t)n * 1024 + tid * 4) = r;
}

// ---------------------------------------------------------------------------
// Launch
// ---------------------------------------------------------------------------
extern "C" void kernel_launch(void* const* d_in, const int* in_sizes, int n_in,
                              void* d_out, int out_size) {
    const float* x   = (const float*)d_in[0];
    const void*  ei  = d_in[1];                 // int32 or int64 (detected)
    const float* W1  = (const float*)d_in[2];
    const float* as1 = (const float*)d_in[3];
    const float* ad1 = (const float*)d_in[4];
    const float* b1  = (const float*)d_in[5];
    const float* g1  = (const float*)d_in[6];
    const float* bt1 = (const float*)d_in[7];
    const float* W2  = (const float*)d_in[8];
    const float* as2 = (const float*)d_in[9];
    const float* ad2 = (const float*)d_in[10];
    const float* b2  = (const float*)d_in[11];
    const float* g2  = (const float*)d_in[12];
    const float* bt2 = (const float*)d_in[13];
    const float* W3  = (const float*)d_in[14];
    const float* as3 = (const float*)d_in[15];
    const float* ad3 = (const float*)d_in[16];
    const float* b3  = (const float*)d_in[17];
    float* out = (float*)d_out;

    float *xw, *agg, *hb, *es, *ed;
    int *cnt, *off, *cur, *csr;
    cudaGetSymbolAddress((void**)&xw,  d_xw);
    cudaGetSymbolAddress((void**)&agg, d_agg);
    cudaGetSymbolAddress((void**)&hb,  d_hb);
    cudaGetSymbolAddress((void**)&es,  d_es);
    cudaGetSymbolAddress((void**)&ed,  d_ed);
    cudaGetSymbolAddress((void**)&cnt, d_cnt);
    cudaGetSymbolAddress((void**)&off, d_off);
    cudaGetSymbolAddress((void**)&cur, d_cur);
    cudaGetSymbolAddress((void**)&csr, d_csr);

    // Detect edge_index dtype, then build CSR by destination (counting sort)
    detect_dtype<<<1, 1>>>((const int*)ei);
    cudaMemsetAsync(cnt, 0, NN * sizeof(int));
    count_edges<<<(ETOT + 255) / 256, 256>>>(ei, cnt);
    scan_offsets<<<1, 1024>>>(cnt, off, cur, NN);
    scatter_edges<<<(ETOT + 255) / 256, 256>>>(ei, cur, csr);

    dim3 g1d((NN + 127) / 128, HIDV / 128);
    dim3 g3d((NN + 127) / 128, COUTV / 128);

    // ---- Layer 1 ----
    sgemm128<<<g1d, 256>>>(x, W1, xw, NN, HIDV, DIN);
    attn_scores<HH, C1V><<<NN, 32 * HH>>>(xw, as1, ad1, es, ed);
    gat_aggregate<HH, C1V><<<NN, 256>>>(xw, es, ed, off, csr, b1, agg);
    ln_elu<<<NN, 256>>>(agg, g1, bt1, hb);

    // ---- Layer 2 ----
    sgemm128<<<g1d, 256>>>(hb, W2, xw, NN, HIDV, HIDV);
    attn_scores<HH, C1V><<<NN, 32 * HH>>>(xw, as2, ad2, es, ed);
    gat_aggregate<HH, C1V><<<NN, 256>>>(xw, es, ed, off, csr, b2, agg);
    ln_elu<<<NN, 256>>>(agg, g2, bt2, hb);

    // ---- Layer 3 ----
    sgemm128<<<g3d, 256>>>(hb, W3, xw, NN, COUTV, HIDV);
    attn_scores<1, COUTV><<<NN, 32>>>(xw, as3, ad3, es, ed);
    gat_aggregate<1, COUTV><<<NN, 256>>>(xw, es, ed, off, csr, b3, out);
}

// round 4
// speedup vs baseline: 1.5525x; 1.2791x over previous
#include <cuda_runtime.h>
#include <cstdint>

// Problem constants (fixed by the reference)
#define NN    20000
#define DIN   128
#define HH    4
#define C1V   256
#define HIDV  1024
#define COUTV 512
#define EE    160000
#define ETOT  (EE + NN)

// ---------------------------------------------------------------------------
// Scratch (device globals: allocation-free per harness rules)
// ---------------------------------------------------------------------------
__device__ float d_xw [NN * HIDV];   // GEMM output / attention features
__device__ float d_agg[NN * HIDV];   // aggregated messages (pre-LN)
__device__ float d_hb [NN * HIDV];   // post LN+ELU activations
__device__ float d_es [NN * HH];
__device__ float d_ed [NN * HH];
__device__ int   d_cnt[NN];
__device__ int   d_off[NN + 1];
__device__ int   d_cur[NN];
__device__ int   d_csr[ETOT];
__device__ int   d_is64;             // edge_index dtype flag (1 = int64)

// ---------------------------------------------------------------------------
// edge_index dtype detection: int64 values < 20000 have zero odd 32-bit words
// ---------------------------------------------------------------------------
__global__ void detect_dtype(const int* __restrict__ ei32) {
    int all_zero = 1;
    #pragma unroll
    for (int i = 1; i < 64; i += 2)
        if (ei32[i] != 0) all_zero = 0;
    d_is64 = all_zero;
}

__device__ __forceinline__ int edge_at(const void* ei, long long idx) {
    if (d_is64) return (int)((const long long*)ei)[idx];
    return ((const int*)ei)[idx];
}

// ---------------------------------------------------------------------------
// CSR-by-dst construction (counting sort)
// ---------------------------------------------------------------------------
__global__ void count_edges(const void* __restrict__ ei, int* __restrict__ cnt) {
    int e = blockIdx.x * blockDim.x + threadIdx.x;
    if (e >= ETOT) return;
    int d = (e < EE) ? edge_at(ei, (long long)EE + e) : (e - EE);
    atomicAdd(&cnt[d], 1);
}

__global__ void scan_offsets(const int* __restrict__ cnt, int* __restrict__ off,
                             int* __restrict__ cur, int n) {
    __shared__ int sh[1024];
    int carry = 0;
    for (int base = 0; base < n; base += 1024) {
        int i = base + threadIdx.x;
        int v = (i < n) ? cnt[i] : 0;
        sh[threadIdx.x] = v;
        __syncthreads();
        for (int o = 1; o < 1024; o <<= 1) {
            int t = (threadIdx.x >= o) ? sh[threadIdx.x - o] : 0;
            __syncthreads();
            sh[threadIdx.x] += t;
            __syncthreads();
        }
        if (i < n) { int ex = carry + sh[threadIdx.x] - v; off[i] = ex; cur[i] = ex; }
        carry += sh[1023];
        __syncthreads();
    }
    if (threadIdx.x == 0) off[n] = carry;
}

__global__ void scatter_edges(const void* __restrict__ ei,
                              int* __restrict__ cur, int* __restrict__ csr) {
    int e = blockIdx.x * blockDim.x + threadIdx.x;
    if (e >= ETOT) return;
    int s = (e < EE) ? edge_at(ei, e)                  : (e - EE);
    int d = (e < EE) ? edge_at(ei, (long long)EE + e)  : (e - EE);
    int pos = atomicAdd(&cur[d], 1);
    csr[pos] = s;
}

// ---------------------------------------------------------------------------
// Tensor-core GEMM: C[M,N] = A[M,K] @ B[K,N], fp32 via 3xTF32 mma.sync.
// 128x128 block tile, 8 warps (4x2), 32x64 warp tile, m16n8k8 mma.
// Requires K%16==0, N%128==0. M guarded.
// ---------------------------------------------------------------------------
#define SPAD 136

__device__ __forceinline__ unsigned f2tf32(float x) {
    unsigned r;
    asm("cvt.rna.tf32.f32 %0, %1;" : "=r"(r) : "f"(x));
    return r;
}
__device__ __forceinline__ void split_tf32(float x, unsigned& hi, unsigned& lo) {
    hi = f2tf32(x);
    lo = f2tf32(x - __uint_as_float(hi));
}
__device__ __forceinline__ void mma_tf32(float* d, const unsigned* a, const unsigned* b) {
    asm volatile(
        "mma.sync.aligned.m16n8k8.row.col.f32.tf32.tf32.f32 "
        "{%0,%1,%2,%3}, {%4,%5,%6,%7}, {%8,%9}, {%0,%1,%2,%3};"
        : "+f"(d[0]), "+f"(d[1]), "+f"(d[2]), "+f"(d[3])
        : "r"(a[0]), "r"(a[1]), "r"(a[2]), "r"(a[3]), "r"(b[0]), "r"(b[1]));
}

__global__ __launch_bounds__(256) void gemm_tc(const float* __restrict__ A,
                                               const float* __restrict__ B,
                                               float* __restrict__ C,
                                               int M, int N, int K) {
    __shared__ float As[2][16][SPAD];   // [k][m]
    __shared__ float Bs[2][16][SPAD];   // [k][n]
    const int tid  = threadIdx.x;
    const int warp = tid >> 5, lane = tid & 31;
    const int g = lane >> 2, t = lane & 3;
    const int wm = (warp & 3) * 32;     // warp row offset in tile
    const int wn = (warp >> 2) * 64;    // warp col offset in tile
    const int m0 = blockIdx.x * 128, n0 = blockIdx.y * 128;

    // Global loader coords (same pattern as before)
    const int ar0 = tid >> 2, ar1 = ar0 + 64;   // A rows within tile
    const int ak  = (tid & 3) * 4;              // A k offset
    const int bk0 = tid >> 5, bk1 = bk0 + 8;    // B k rows
    const int bn  = (tid & 31) * 4;             // B n offset
    const int gm_a0 = m0 + ar0, gm_a1 = m0 + ar1;
    const int nt_tiles = K / 16;

    float4 av0, av1, bv0, bv1;
    const float4 z4 = make_float4(0.f, 0.f, 0.f, 0.f);

    // Prefetch tile 0
    av0 = (gm_a0 < M) ? *(const float4*)&A[(size_t)gm_a0 * K + ak] : z4;
    av1 = (gm_a1 < M) ? *(const float4*)&A[(size_t)gm_a1 * K + ak] : z4;
    bv0 = *(const float4*)&B[(size_t)bk0 * N + n0 + bn];
    bv1 = *(const float4*)&B[(size_t)bk1 * N + n0 + bn];
    As[0][ak + 0][ar0] = av0.x; As[0][ak + 1][ar0] = av0.y;
    As[0][ak + 2][ar0] = av0.z; As[0][ak + 3][ar0] = av0.w;
    As[0][ak + 0][ar1] = av1.x; As[0][ak + 1][ar1] = av1.y;
    As[0][ak + 2][ar1] = av1.z; As[0][ak + 3][ar1] = av1.w;
    *(float4*)&Bs[0][bk0][bn] = bv0;
    *(float4*)&Bs[0][bk1][bn] = bv1;
    __syncthreads();

    float acc[2][8][4] = {};
    int buf = 0;
    for (int kt = 0; kt < nt_tiles; kt++) {
        if (kt + 1 < nt_tiles) {
            int k0 = (kt + 1) * 16;
            av0 = (gm_a0 < M) ? *(const float4*)&A[(size_t)gm_a0 * K + k0 + ak] : z4;
            av1 = (gm_a1 < M) ? *(const float4*)&A[(size_t)gm_a1 * K + k0 + ak] : z4;
            bv0 = *(const float4*)&B[(size_t)(k0 + bk0) * N + n0 + bn];
            bv1 = *(const float4*)&B[(size_t)(k0 + bk1) * N + n0 + bn];
        }
        #pragma unroll
        for (int kb = 0; kb < 16; kb += 8) {
            unsigned ahi[2][4], alo[2][4], bhi[8][2], blo[8][2];
            #pragma unroll
            for (int mt = 0; mt < 2; mt++) {
                int mb = wm + mt * 16;
                float a0 = As[buf][kb + t    ][mb + g];
                float a1 = As[buf][kb + t    ][mb + g + 8];
                float a2 = As[buf][kb + t + 4][mb + g];
                float a3 = As[buf][kb + t + 4][mb + g + 8];
                split_tf32(a0, ahi[mt][0], alo[mt][0]);
                split_tf32(a1, ahi[mt][1], alo[mt][1]);
                split_tf32(a2, ahi[mt][2], alo[mt][2]);
                split_tf32(a3, ahi[mt][3], alo[mt][3]);
            }
            #pragma unroll
            for (int nt = 0; nt < 8; nt++) {
                int nb = wn + nt * 8 + g;
                float b0 = Bs[buf][kb + t    ][nb];
                float b1 = Bs[buf][kb + t + 4][nb];
                split_tf32(b0, bhi[nt][0], blo[nt][0]);
                split_tf32(b1, bhi[nt][1], blo[nt][1]);
            }
            #pragma unroll
            for (int mt = 0; mt < 2; mt++)
                #pragma unroll
                for (int nt = 0; nt < 8; nt++) {
                    mma_tf32(acc[mt][nt], ahi[mt], bhi[nt]);
                    mma_tf32(acc[mt][nt], ahi[mt], blo[nt]);
                    mma_tf32(acc[mt][nt], alo[mt], bhi[nt]);
                }
        }
        if (kt + 1 < nt_tiles) {
            int nb2 = buf ^ 1;
            As[nb2][ak + 0][ar0] = av0.x; As[nb2][ak + 1][ar0] = av0.y;
            As[nb2][ak + 2][ar0] = av0.z; As[nb2][ak + 3][ar0] = av0.w;
            As[nb2][ak + 0][ar1] = av1.x; As[nb2][ak + 1][ar1] = av1.y;
            As[nb2][ak + 2][ar1] = av1.z; As[nb2][ak + 3][ar1] = av1.w;
            *(float4*)&Bs[nb2][bk0][bn] = bv0;
            *(float4*)&Bs[nb2][bk1][bn] = bv1;
        }
        __syncthreads();
        buf ^= 1;
    }

    // Epilogue: fragment c0,c1 = (row g, cols 2t,2t+1); c2,c3 = row g+8
    #pragma unroll
    for (int mt = 0; mt < 2; mt++) {
        #pragma unroll
        for (int nt = 0; nt < 8; nt++) {
            const float* dd = acc[mt][nt];
            int m = m0 + wm + mt * 16 + g;
            int n = n0 + wn + nt * 8 + 2 * t;
            if (m < M)
                *(float2*)&C[(size_t)m * N + n] = make_float2(dd[0], dd[1]);
            if (m + 8 < M)
                *(float2*)&C[(size_t)(m + 8) * N + n] = make_float2(dd[2], dd[3]);
        }
    }
}

// ---------------------------------------------------------------------------
// Per-node attention scores: es[n,h] = <xw[n,h,:], a_src[h,:]>, ed likewise
// ---------------------------------------------------------------------------
template<int H, int C>
__global__ void attn_scores(const float* __restrict__ xw,
                            const float* __restrict__ asrc,
                            const float* __restrict__ adst,
                            float* __restrict__ es, float* __restrict__ ed) {
    int n = blockIdx.x;
    int w = threadIdx.x >> 5, lane = threadIdx.x & 31;
    const float* row = xw + (size_t)n * H * C + w * C;
    float ss = 0.f, sd = 0.f;
    for (int c = lane; c < C; c += 32) {
        float v = row[c];
        ss += v * asrc[w * C + c];
        sd += v * adst[w * C + c];
    }
    #pragma unroll
    for (int o = 16; o; o >>= 1) {
        ss += __shfl_down_sync(0xffffffffu, ss, o);
        sd += __shfl_down_sync(0xffffffffu, sd, o);
    }
    if (!lane) { es[n * H + w] = ss; ed[n * H + w] = sd; }
}

// ---------------------------------------------------------------------------
// GAT aggregation: one block per dst node, segment softmax + weighted gather.
// ---------------------------------------------------------------------------
template<int H, int C>
__global__ __launch_bounds__(256) void gat_aggregate(
        const float* __restrict__ xw, const float* __restrict__ es,
        const float* __restrict__ ed, const int* __restrict__ off,
        const int* __restrict__ csr, const float* __restrict__ bias,
        float* __restrict__ out) {
    constexpr int HC = H * C;
    constexpr int F  = HC / 256;
    int n = blockIdx.x, tid = threadIdx.x;
    __shared__ float ed_sh[H], mx_sh[H], id_sh[H], red[256];
    __shared__ float alpha_sh[64 * H];
    __shared__ int   src_sh[64];
    if (tid < H) ed_sh[tid] = ed[n * H + tid];
    __syncthreads();
    int start = off[n];
    int deg   = off[n + 1] - start;   // >= 1 always (self loop)

    // Phase A: max per head
    float lmax[H];
    #pragma unroll
    for (int h = 0; h < H; h++) lmax[h] = -3.4e38f;
    for (int i = tid; i < deg; i += 256) {
        int s = csr[start + i];
        #pragma unroll
        for (int h = 0; h < H; h++) {
            float e = es[s * H + h] + ed_sh[h];
            e = (e > 0.f) ? e : 0.2f * e;
            lmax[h] = fmaxf(lmax[h], e);
        }
    }
    #pragma unroll
    for (int h = 0; h < H; h++) {
        red[tid] = lmax[h]; __syncthreads();
        for (int o = 128; o; o >>= 1) {
            if (tid < o) red[tid] = fmaxf(red[tid], red[tid + o]);
            __syncthreads();
        }
        if (!tid) mx_sh[h] = red[0];
        __syncthreads();
    }

    // Phase B: denominator per head
    float lsum[H];
    #pragma unroll
    for (int h = 0; h < H; h++) lsum[h] = 0.f;
    for (int i = tid; i < deg; i += 256) {
        int s = csr[start + i];
        #pragma unroll
        for (int h = 0; h < H; h++) {
            float e = es[s * H + h] + ed_sh[h];
            e = (e > 0.f) ? e : 0.2f * e;
            lsum[h] += expf(e - mx_sh[h]);
        }
    }
    #pragma unroll
    for (int h = 0; h < H; h++) {
        red[tid] = lsum[h]; __syncthreads();
        for (int o = 128; o; o >>= 1) {
            if (tid < o) red[tid] += red[tid + o];
            __syncthreads();
        }
        if (!tid) id_sh[h] = 1.f / (red[0] + 1e-16f);
        __syncthreads();
    }

    // Phase C: weighted feature accumulation, chunks of 64 edges
    float acc[F];
    #pragma unroll
    for (int k = 0; k < F; k++) acc[k] = 0.f;
    const int head = (tid * F) / C;
    for (int c0 = 0; c0 < deg; c0 += 64) {
        int nc = min(64, deg - c0);
        if (tid < nc * H) {
            int j = tid / H, h = tid - j * H;
            int s = csr[start + c0 + j];
            if (h == 0) src_sh[j] = s;
            float e = es[s * H + h] + ed_sh[h];
            e = (e > 0.f) ? e : 0.2f * e;
            alpha_sh[j * H + h] = expf(e - mx_sh[h]) * id_sh[h];
        }
        __syncthreads();
        for (int j = 0; j < nc; j++) {
            int s = src_sh[j];
            float a = alpha_sh[j * H + head];
            const float* row = xw + (size_t)s * HC + tid * F;
            if constexpr (F == 4) {
                float4 v = *reinterpret_cast<const float4*>(row);
                acc[0] = fmaf(a, v.x, acc[0]); acc[1] = fmaf(a, v.y, acc[1]);
                acc[2] = fmaf(a, v.z, acc[2]); acc[3] = fmaf(a, v.w, acc[3]);
            } else {
                float2 v = *reinterpret_cast<const float2*>(row);
                acc[0] = fmaf(a, v.x, acc[0]); acc[1] = fmaf(a, v.y, acc[1]);
            }
        }
        __syncthreads();
    }
    float* o = out + (size_t)n * HC + tid * F;
    #pragma unroll
    for (int k = 0; k < F; k++) o[k] = acc[k] + bias[tid * F + k];
}

// ---------------------------------------------------------------------------
// Fused LayerNorm + ELU over rows of width 1024 (input already has GAT bias)
// ---------------------------------------------------------------------------
__global__ __launch_bounds__(256) void ln_elu(const float* __restrict__ in,
                                              const float* __restrict__ g,
                                              const float* __restrict__ b,
                                              float* __restrict__ out) {
    int n = blockIdx.x, tid = threadIdx.x;
    const float4 v = *reinterpret_cast<const float4*>(in + (size_t)n * 1024 + tid * 4);
    float s  = v.x + v.y + v.z + v.w;
    float sq = v.x * v.x + v.y * v.y + v.z * v.z + v.w * v.w;
    __shared__ float r1[256], r2[256];
    r1[tid] = s; r2[tid] = sq; __syncthreads();
    for (int o = 128; o; o >>= 1) {
        if (tid < o) { r1[tid] += r1[tid + o]; r2[tid] += r2[tid + o]; }
        __syncthreads();
    }
    float mean = r1[0] * (1.f / 1024.f);
    float var  = r2[0] * (1.f / 1024.f) - mean * mean;
    float rstd = rsqrtf(var + 1e-5f);
    const float4 gv = *reinterpret_cast<const float4*>(g + tid * 4);
    const float4 bv = *reinterpret_cast<const float4*>(b + tid * 4);
    float xin[4] = {v.x, v.y, v.z, v.w};
    float gg[4]  = {gv.x, gv.y, gv.z, gv.w};
    float bb[4]  = {bv.x, bv.y, bv.z, bv.w};
    float4 r;
    float* rp = &r.x;
    #pragma unroll
    for (int k = 0; k < 4; k++) {
        float y = (xin[k] - mean) * rstd * gg[k] + bb[k];
        rp[k] = (y > 0.f) ? y : expm1f(y);
    }
    *reinterpret_cast<float4*>(out + (size_t)n * 1024 + tid * 4) = r;
}

// ---------------------------------------------------------------------------
// Launch
// ---------------------------------------------------------------------------
extern "C" void kernel_launch(void* const* d_in, const int* in_sizes, int n_in,
                              void* d_out, int out_size) {
    const float* x   = (const float*)d_in[0];
    const void*  ei  = d_in[1];                 // int32 or int64 (detected)
    const float* W1  = (const float*)d_in[2];
    const float* as1 = (const float*)d_in[3];
    const float* ad1 = (const float*)d_in[4];
    const float* b1  = (const float*)d_in[5];
    const float* g1  = (const float*)d_in[6];
    const float* bt1 = (const float*)d_in[7];
    const float* W2  = (const float*)d_in[8];
    const float* as2 = (const float*)d_in[9];
    const float* ad2 = (const float*)d_in[10];
    const float* b2  = (const float*)d_in[11];
    const float* g2  = (const float*)d_in[12];
    const float* bt2 = (const float*)d_in[13];
    const float* W3  = (const float*)d_in[14];
    const float* as3 = (const float*)d_in[15];
    const float* ad3 = (const float*)d_in[16];
    const float* b3  = (const float*)d_in[17];
    float* out = (float*)d_out;

    float *xw, *agg, *hb, *es, *ed;
    int *cnt, *off, *cur, *csr;
    cudaGetSymbolAddress((void**)&xw,  d_xw);
    cudaGetSymbolAddress((void**)&agg, d_agg);
    cudaGetSymbolAddress((void**)&hb,  d_hb);
    cudaGetSymbolAddress((void**)&es,  d_es);
    cudaGetSymbolAddress((void**)&ed,  d_ed);
    cudaGetSymbolAddress((void**)&cnt, d_cnt);
    cudaGetSymbolAddress((void**)&off, d_off);
    cudaGetSymbolAddress((void**)&cur, d_cur);
    cudaGetSymbolAddress((void**)&csr, d_csr);

    dim3 g1d((NN + 127) / 128, HIDV / 128);
    dim3 g3d((NN + 127) / 128, COUTV / 128);

    // CSR build interleaved with layer-1 GEMM so gemm_tc lands in the ncu
    // profiling slot (launch #5). scatter completes before gat_aggregate.
    detect_dtype<<<1, 1>>>((const int*)ei);
    cudaMemsetAsync(cnt, 0, NN * sizeof(int));
    count_edges<<<(ETOT + 255) / 256, 256>>>(ei, cnt);
    scan_offsets<<<1, 1024>>>(cnt, off, cur, NN);

    // ---- Layer 1 ----
    gemm_tc<<<g1d, 256>>>(x, W1, xw, NN, HIDV, DIN);
    scatter_edges<<<(ETOT + 255) / 256, 256>>>(ei, cur, csr);
    attn_scores<HH, C1V><<<NN, 32 * HH>>>(xw, as1, ad1, es, ed);
    gat_aggregate<HH, C1V><<<NN, 256>>>(xw, es, ed, off, csr, b1, agg);
    ln_elu<<<NN, 256>>>(agg, g1, bt1, hb);

    // ---- Layer 2 ----
    gemm_tc<<<g1d, 256>>>(hb, W2, xw, NN, HIDV, HIDV);
    attn_scores<HH, C1V><<<NN, 32 * HH>>>(xw, as2, ad2, es, ed);
    gat_aggregate<HH, C1V><<<NN, 256>>>(xw, es, ed, off, csr, b2, agg);
    ln_elu<<<NN, 256>>>(agg, g2, bt2, hb);

    // ---- Layer 3 ----
    gemm_tc<<<g3d, 256>>>(hb, W3, xw, NN, COUTV, HIDV);
    attn_scores<1, COUTV><<<NN, 32>>>(xw, as3, ad3, es, ed);
    gat_aggregate<1, COUTV><<<NN, 256>>>(xw, es, ed, off, csr, b3, out);
}

// round 5
// speedup vs baseline: 1.7486x; 1.1263x over previous
#include <cuda_runtime.h>
#include <cstdint>

// Problem constants (fixed by the reference)
#define NN    20000
#define DIN   128
#define HH    4
#define C1V   256
#define HIDV  1024
#define COUTV 512
#define EE    160000
#define ETOT  (EE + NN)

// ---------------------------------------------------------------------------
// Scratch (device globals: allocation-free per harness rules)
// ---------------------------------------------------------------------------
__device__ float d_xw [NN * HIDV];   // GEMM output / attention features
__device__ float d_agg[NN * HIDV];   // aggregated messages (pre-LN)
__device__ float d_hb [NN * HIDV];   // post LN+ELU activations
__device__ float d_es [NN * HH];
__device__ float d_ed [NN * HH];
__device__ int   d_cnt[NN];
__device__ int   d_off[NN + 1];
__device__ int   d_cur[NN];
__device__ int   d_csr[ETOT];
__device__ int   d_is64;             // edge_index dtype flag (1 = int64)

// ---------------------------------------------------------------------------
// edge_index dtype detection: int64 values < 20000 have zero odd 32-bit words
// ---------------------------------------------------------------------------
__global__ void detect_dtype(const int* __restrict__ ei32) {
    int all_zero = 1;
    #pragma unroll
    for (int i = 1; i < 64; i += 2)
        if (ei32[i] != 0) all_zero = 0;
    d_is64 = all_zero;
}

__device__ __forceinline__ int edge_at(const void* ei, long long idx) {
    if (d_is64) return (int)((const long long*)ei)[idx];
    return ((const int*)ei)[idx];
}

// ---------------------------------------------------------------------------
// CSR-by-dst construction (counting sort)
// ---------------------------------------------------------------------------
__global__ void count_edges(const void* __restrict__ ei, int* __restrict__ cnt) {
    int e = blockIdx.x * blockDim.x + threadIdx.x;
    if (e >= ETOT) return;
    int d = (e < EE) ? edge_at(ei, (long long)EE + e) : (e - EE);
    atomicAdd(&cnt[d], 1);
}

__global__ void scan_offsets(const int* __restrict__ cnt, int* __restrict__ off,
                             int* __restrict__ cur, int n) {
    __shared__ int sh[1024];
    int carry = 0;
    for (int base = 0; base < n; base += 1024) {
        int i = base + threadIdx.x;
        int v = (i < n) ? cnt[i] : 0;
        sh[threadIdx.x] = v;
        __syncthreads();
        for (int o = 1; o < 1024; o <<= 1) {
            int t = (threadIdx.x >= o) ? sh[threadIdx.x - o] : 0;
            __syncthreads();
            sh[threadIdx.x] += t;
            __syncthreads();
        }
        if (i < n) { int ex = carry + sh[threadIdx.x] - v; off[i] = ex; cur[i] = ex; }
        carry += sh[1023];
        __syncthreads();
    }
    if (threadIdx.x == 0) off[n] = carry;
}

__global__ void scatter_edges(const void* __restrict__ ei,
                              int* __restrict__ cur, int* __restrict__ csr) {
    int e = blockIdx.x * blockDim.x + threadIdx.x;
    if (e >= ETOT) return;
    int s = (e < EE) ? edge_at(ei, e)                  : (e - EE);
    int d = (e < EE) ? edge_at(ei, (long long)EE + e)  : (e - EE);
    int pos = atomicAdd(&cur[d], 1);
    csr[pos] = s;
}

// ---------------------------------------------------------------------------
// Tensor-core GEMM: C[M,N] = A[M,K] @ B[K,N], fp32 via 3xTF32 mma.sync.
// 128x128 block tile, 8 warps (4x2), 32x64 warp tile, m16n8k8 mma.
// hi/lo tf32 split precomputed at smem-store time (no cvt in mainloop).
// Requires K%16==0, N%128==0. M guarded.
// ---------------------------------------------------------------------------
#define SPAD 136
#define TSLOT (16 * SPAD)                 // floats per (buf-slice) tile row set
#define SM_FLOATS (4 * 2 * TSLOT)         // 4 arrays x 2 buffers
#define SM_BYTES  (SM_FLOATS * 4)         // 69632

__device__ __forceinline__ unsigned f2tf32(float x) {
    unsigned r;
    asm("cvt.rna.tf32.f32 %0, %1;" : "=r"(r) : "f"(x));
    return r;
}
__device__ __forceinline__ void mma_tf32(float* d, const unsigned* a, const unsigned* b) {
    asm volatile(
        "mma.sync.aligned.m16n8k8.row.col.f32.tf32.tf32.f32 "
        "{%0,%1,%2,%3}, {%4,%5,%6,%7}, {%8,%9}, {%0,%1,%2,%3};"
        : "+f"(d[0]), "+f"(d[1]), "+f"(d[2]), "+f"(d[3])
        : "r"(a[0]), "r"(a[1]), "r"(a[2]), "r"(a[3]), "r"(b[0]), "r"(b[1]));
}

__global__ __launch_bounds__(256, 2) void gemm_tc(const float* __restrict__ A,
                                                  const float* __restrict__ B,
                                                  float* __restrict__ C,
                                                  int M, int N, int K) {
    extern __shared__ float sm[];
    float* AH = sm;                       // [2][16][SPAD] A hi
    float* AL = sm + 2 * TSLOT;           // A lo
    float* BH = sm + 4 * TSLOT;           // B hi
    float* BL = sm + 6 * TSLOT;           // B lo

    const int tid  = threadIdx.x;
    const int warp = tid >> 5, lane = tid & 31;
    const int g = lane >> 2, t = lane & 3;
    const int wm = (warp & 3) * 32;       // warp row offset in tile
    const int wn = (warp >> 2) * 64;      // warp col offset in tile
    const int m0 = blockIdx.x * 128, n0 = blockIdx.y * 128;

    // Global loader coords
    const int ar0 = tid >> 2, ar1 = ar0 + 64;   // A rows within tile
    const int ak  = (tid & 3) * 4;              // A k offset
    const int bk0 = tid >> 5, bk1 = bk0 + 8;    // B k rows
    const int bn  = (tid & 31) * 4;             // B n offset
    const int gm_a0 = m0 + ar0, gm_a1 = m0 + ar1;
    const int nt_tiles = K / 16;

    float4 av0, av1, bv0, bv1;
    const float4 z4 = make_float4(0.f, 0.f, 0.f, 0.f);

    // smem store helpers (split to hi/lo at store time)
    auto storeA = [&](int buf, const float4& v, int row) {
        float* ahp = AH + (buf * 16 + ak) * SPAD + row;
        float* alp = AL + (buf * 16 + ak) * SPAD + row;
        const float vv[4] = {v.x, v.y, v.z, v.w};
        #pragma unroll
        for (int i = 0; i < 4; i++) {
            unsigned hi = f2tf32(vv[i]);
            unsigned lo = f2tf32(vv[i] - __uint_as_float(hi));
            ahp[i * SPAD] = __uint_as_float(hi);
            alp[i * SPAD] = __uint_as_float(lo);
        }
    };
    auto storeB = [&](int buf, const float4& v, int krow) {
        const float vv[4] = {v.x, v.y, v.z, v.w};
        float4 h4, l4;
        float* hp = &h4.x; float* lp = &l4.x;
        #pragma unroll
        for (int i = 0; i < 4; i++) {
            unsigned hi = f2tf32(vv[i]);
            hp[i] = __uint_as_float(hi);
            lp[i] = __uint_as_float(f2tf32(vv[i] - __uint_as_float(hi)));
        }
        *(float4*)&BH[(buf * 16 + krow) * SPAD + bn] = h4;
        *(float4*)&BL[(buf * 16 + krow) * SPAD + bn] = l4;
    };

    // Prefetch + store tile 0
    av0 = (gm_a0 < M) ? *(const float4*)&A[(size_t)gm_a0 * K + ak] : z4;
    av1 = (gm_a1 < M) ? *(const float4*)&A[(size_t)gm_a1 * K + ak] : z4;
    bv0 = *(const float4*)&B[(size_t)bk0 * N + n0 + bn];
    bv1 = *(const float4*)&B[(size_t)bk1 * N + n0 + bn];
    storeA(0, av0, ar0); storeA(0, av1, ar1);
    storeB(0, bv0, bk0); storeB(0, bv1, bk1);
    __syncthreads();

    float acc[2][8][4] = {};
    int buf = 0;
    for (int kt = 0; kt < nt_tiles; kt++) {
        if (kt + 1 < nt_tiles) {
            int k0 = (kt + 1) * 16;
            av0 = (gm_a0 < M) ? *(const float4*)&A[(size_t)gm_a0 * K + k0 + ak] : z4;
            av1 = (gm_a1 < M) ? *(const float4*)&A[(size_t)gm_a1 * K + k0 + ak] : z4;
            bv0 = *(const float4*)&B[(size_t)(k0 + bk0) * N + n0 + bn];
            bv1 = *(const float4*)&B[(size_t)(k0 + bk1) * N + n0 + bn];
        }
        #pragma unroll
        for (int kb = 0; kb < 16; kb += 8) {
            const float* ahb = AH + (buf * 16 + kb) * SPAD;
            const float* alb = AL + (buf * 16 + kb) * SPAD;
            const float* bhb = BH + (buf * 16 + kb) * SPAD;
            const float* blb = BL + (buf * 16 + kb) * SPAD;
            unsigned ahi[2][4], alo[2][4];
            #pragma unroll
            for (int mt = 0; mt < 2; mt++) {
                int mb = wm + mt * 16 + g;
                ahi[mt][0] = __float_as_uint(ahb[ t      * SPAD + mb]);
                ahi[mt][1] = __float_as_uint(ahb[ t      * SPAD + mb + 8]);
                ahi[mt][2] = __float_as_uint(ahb[(t + 4) * SPAD + mb]);
                ahi[mt][3] = __float_as_uint(ahb[(t + 4) * SPAD + mb + 8]);
                alo[mt][0] = __float_as_uint(alb[ t      * SPAD + mb]);
                alo[mt][1] = __float_as_uint(alb[ t      * SPAD + mb + 8]);
                alo[mt][2] = __float_as_uint(alb[(t + 4) * SPAD + mb]);
                alo[mt][3] = __float_as_uint(alb[(t + 4) * SPAD + mb + 8]);
            }
            #pragma unroll
            for (int nt = 0; nt < 8; nt++) {
                int nb2 = wn + nt * 8 + g;
                unsigned bh[2], bl[2];
                bh[0] = __float_as_uint(bhb[ t      * SPAD + nb2]);
                bh[1] = __float_as_uint(bhb[(t + 4) * SPAD + nb2]);
                bl[0] = __float_as_uint(blb[ t      * SPAD + nb2]);
                bl[1] = __float_as_uint(blb[(t + 4) * SPAD + nb2]);
                mma_tf32(acc[0][nt], ahi[0], bh);
                mma_tf32(acc[1][nt], ahi[1], bh);
                mma_tf32(acc[0][nt], ahi[0], bl);
                mma_tf32(acc[1][nt], ahi[1], bl);
                mma_tf32(acc[0][nt], alo[0], bh);
                mma_tf32(acc[1][nt], alo[1], bh);
            }
        }
        if (kt + 1 < nt_tiles) {
            int nb = buf ^ 1;
            storeA(nb, av0, ar0); storeA(nb, av1, ar1);
            storeB(nb, bv0, bk0); storeB(nb, bv1, bk1);
        }
        __syncthreads();
        buf ^= 1;
    }

    // Epilogue: fragment c0,c1 = (row g, cols 2t,2t+1); c2,c3 = row g+8
    #pragma unroll
    for (int mt = 0; mt < 2; mt++) {
        #pragma unroll
        for (int nt = 0; nt < 8; nt++) {
            const float* dd = acc[mt][nt];
            int m = m0 + wm + mt * 16 + g;
            int n = n0 + wn + nt * 8 + 2 * t;
            if (m < M)
                *(float2*)&C[(size_t)m * N + n] = make_float2(dd[0], dd[1]);
            if (m + 8 < M)
                *(float2*)&C[(size_t)(m + 8) * N + n] = make_float2(dd[2], dd[3]);
        }
    }
}

// ---------------------------------------------------------------------------
// Per-node attention scores: es[n,h] = <xw[n,h,:], a_src[h,:]>, ed likewise
// ---------------------------------------------------------------------------
template<int H, int C>
__global__ void attn_scores(const float* __restrict__ xw,
                            const float* __restrict__ asrc,
                            const float* __restrict__ adst,
                            float* __restrict__ es, float* __restrict__ ed) {
    int n = blockIdx.x;
    int w = threadIdx.x >> 5, lane = threadIdx.x & 31;
    const float* row = xw + (size_t)n * H * C + w * C;
    float ss = 0.f, sd = 0.f;
    for (int c = lane; c < C; c += 32) {
        float v = row[c];
        ss += v * asrc[w * C + c];
        sd += v * adst[w * C + c];
    }
    #pragma unroll
    for (int o = 16; o; o >>= 1) {
        ss += __shfl_down_sync(0xffffffffu, ss, o);
        sd += __shfl_down_sync(0xffffffffu, sd, o);
    }
    if (!lane) { es[n * H + w] = ss; ed[n * H + w] = sd; }
}

// ---------------------------------------------------------------------------
// GAT aggregation: one block per dst node, segment softmax + weighted gather.
// ---------------------------------------------------------------------------
template<int H, int C>
__global__ __launch_bounds__(256) void gat_aggregate(
        const float* __restrict__ xw, const float* __restrict__ es,
        const float* __restrict__ ed, const int* __restrict__ off,
        const int* __restrict__ csr, const float* __restrict__ bias,
        float* __restrict__ out) {
    constexpr int HC = H * C;
    constexpr int F  = HC / 256;
    int n = blockIdx.x, tid = threadIdx.x;
    __shared__ float ed_sh[H], mx_sh[H], id_sh[H], red[256];
    __shared__ float alpha_sh[64 * H];
    __shared__ int   src_sh[64];
    if (tid < H) ed_sh[tid] = ed[n * H + tid];
    __syncthreads();
    int start = off[n];
    int deg   = off[n + 1] - start;   // >= 1 always (self loop)

    // Phase A: max per head
    float lmax[H];
    #pragma unroll
    for (int h = 0; h < H; h++) lmax[h] = -3.4e38f;
    for (int i = tid; i < deg; i += 256) {
        int s = csr[start + i];
        #pragma unroll
        for (int h = 0; h < H; h++) {
            float e = es[s * H + h] + ed_sh[h];
            e = (e > 0.f) ? e : 0.2f * e;
            lmax[h] = fmaxf(lmax[h], e);
        }
    }
    #pragma unroll
    for (int h = 0; h < H; h++) {
        red[tid] = lmax[h]; __syncthreads();
        for (int o = 128; o; o >>= 1) {
            if (tid < o) red[tid] = fmaxf(red[tid], red[tid + o]);
            __syncthreads();
        }
        if (!tid) mx_sh[h] = red[0];
        __syncthreads();
    }

    // Phase B: denominator per head
    float lsum[H];
    #pragma unroll
    for (int h = 0; h < H; h++) lsum[h] = 0.f;
    for (int i = tid; i < deg; i += 256) {
        int s = csr[start + i];
        #pragma unroll
        for (int h = 0; h < H; h++) {
            float e = es[s * H + h] + ed_sh[h];
            e = (e > 0.f) ? e : 0.2f * e;
            lsum[h] += expf(e - mx_sh[h]);
        }
    }
    #pragma unroll
    for (int h = 0; h < H; h++) {
        red[tid] = lsum[h]; __syncthreads();
        for (int o = 128; o; o >>= 1) {
            if (tid < o) red[tid] += red[tid + o];
            __syncthreads();
        }
        if (!tid) id_sh[h] = 1.f / (red[0] + 1e-16f);
        __syncthreads();
    }

    // Phase C: weighted feature accumulation, chunks of 64 edges
    float acc[F];
    #pragma unroll
    for (int k = 0; k < F; k++) acc[k] = 0.f;
    const int head = (tid * F) / C;
    for (int c0 = 0; c0 < deg; c0 += 64) {
        int nc = min(64, deg - c0);
        if (tid < nc * H) {
            int j = tid / H, h = tid - j * H;
            int s = csr[start + c0 + j];
            if (h == 0) src_sh[j] = s;
            float e = es[s * H + h] + ed_sh[h];
            e = (e > 0.f) ? e : 0.2f * e;
            alpha_sh[j * H + h] = expf(e - mx_sh[h]) * id_sh[h];
        }
        __syncthreads();
        for (int j = 0; j < nc; j++) {
            int s = src_sh[j];
            float a = alpha_sh[j * H + head];
            const float* row = xw + (size_t)s * HC + tid * F;
            if constexpr (F == 4) {
                float4 v = *reinterpret_cast<const float4*>(row);
                acc[0] = fmaf(a, v.x, acc[0]); acc[1] = fmaf(a, v.y, acc[1]);
                acc[2] = fmaf(a, v.z, acc[2]); acc[3] = fmaf(a, v.w, acc[3]);
            } else {
                float2 v = *reinterpret_cast<const float2*>(row);
                acc[0] = fmaf(a, v.x, acc[0]); acc[1] = fmaf(a, v.y, acc[1]);
            }
        }
        __syncthreads();
    }
    float* o = out + (size_t)n * HC + tid * F;
    #pragma unroll
    for (int k = 0; k < F; k++) o[k] = acc[k] + bias[tid * F + k];
}

// ---------------------------------------------------------------------------
// Fused LayerNorm + ELU over rows of width 1024 (input already has GAT bias)
// ---------------------------------------------------------------------------
__global__ __launch_bounds__(256) void ln_elu(const float* __restrict__ in,
                                              const float* __restrict__ g,
                                              const float* __restrict__ b,
                                              float* __restrict__ out) {
    int n = blockIdx.x, tid = threadIdx.x;
    const float4 v = *reinterpret_cast<const float4*>(in + (size_t)n * 1024 + tid * 4);
    float s  = v.x + v.y + v.z + v.w;
    float sq = v.x * v.x + v.y * v.y + v.z * v.z + v.w * v.w;
    __shared__ float r1[256], r2[256];
    r1[tid] = s; r2[tid] = sq; __syncthreads();
    for (int o = 128; o; o >>= 1) {
        if (tid < o) { r1[tid] += r1[tid + o]; r2[tid] += r2[tid + o]; }
        __syncthreads();
    }
    float mean = r1[0] * (1.f / 1024.f);
    float var  = r2[0] * (1.f / 1024.f) - mean * mean;
    float rstd = rsqrtf(var + 1e-5f);
    const float4 gv = *reinterpret_cast<const float4*>(g + tid * 4);
    const float4 bv = *reinterpret_cast<const float4*>(b + tid * 4);
    float xin[4] = {v.x, v.y, v.z, v.w};
    float gg[4]  = {gv.x, gv.y, gv.z, gv.w};
    float bb[4]  = {bv.x, bv.y, bv.z, bv.w};
    float4 r;
    float* rp = &r.x;
    #pragma unroll
    for (int k = 0; k < 4; k++) {
        float y = (xin[k] - mean) * rstd * gg[k] + bb[k];
        rp[k] = (y > 0.f) ? y : expm1f(y);
    }
    *reinterpret_cast<float4*>(out + (size_t)n * 1024 + tid * 4) = r;
}

// ---------------------------------------------------------------------------
// Launch
// ---------------------------------------------------------------------------
extern "C" void kernel_launch(void* const* d_in, const int* in_sizes, int n_in,
                              void* d_out, int out_size) {
    const float* x   = (const float*)d_in[0];
    const void*  ei  = d_in[1];                 // int32 or int64 (detected)
    const float* W1  = (const float*)d_in[2];
    const float* as1 = (const float*)d_in[3];
    const float* ad1 = (const float*)d_in[4];
    const float* b1  = (const float*)d_in[5];
    const float* g1  = (const float*)d_in[6];
    const float* bt1 = (const float*)d_in[7];
    const float* W2  = (const float*)d_in[8];
    const float* as2 = (const float*)d_in[9];
    const float* ad2 = (const float*)d_in[10];
    const float* b2  = (const float*)d_in[11];
    const float* g2  = (const float*)d_in[12];
    const float* bt2 = (const float*)d_in[13];
    const float* W3  = (const float*)d_in[14];
    const float* as3 = (const float*)d_in[15];
    const float* ad3 = (const float*)d_in[16];
    const float* b3  = (const float*)d_in[17];
    float* out = (float*)d_out;

    float *xw, *agg, *hb, *es, *ed;
    int *cnt, *off, *cur, *csr;
    cudaGetSymbolAddress((void**)&xw,  d_xw);
    cudaGetSymbolAddress((void**)&agg, d_agg);
    cudaGetSymbolAddress((void**)&hb,  d_hb);
    cudaGetSymbolAddress((void**)&es,  d_es);
    cudaGetSymbolAddress((void**)&ed,  d_ed);
    cudaGetSymbolAddress((void**)&cnt, d_cnt);
    cudaGetSymbolAddress((void**)&off, d_off);
    cudaGetSymbolAddress((void**)&cur, d_cur);
    cudaGetSymbolAddress((void**)&csr, d_csr);

    static int smem_set = 0;
    if (!smem_set) {
        cudaFuncSetAttribute(gemm_tc, cudaFuncAttributeMaxDynamicSharedMemorySize,
                             SM_BYTES);
        smem_set = 1;
    }

    dim3 g1d((NN + 127) / 128, HIDV / 128);
    dim3 g3d((NN + 127) / 128, COUTV / 128);

    // CSR build interleaved with layer-1 GEMM so gemm_tc lands in the ncu
    // profiling slot (launch #5). scatter completes before gat_aggregate.
    detect_dtype<<<1, 1>>>((const int*)ei);
    cudaMemsetAsync(cnt, 0, NN * sizeof(int));
    count_edges<<<(ETOT + 255) / 256, 256>>>(ei, cnt);
    scan_offsets<<<1, 1024>>>(cnt, off, cur, NN);

    // ---- Layer 1 ----
    gemm_tc<<<g1d, 256, SM_BYTES>>>(x, W1, xw, NN, HIDV, DIN);
    scatter_edges<<<(ETOT + 255) / 256, 256>>>(ei, cur, csr);
    attn_scores<HH, C1V><<<NN, 32 * HH>>>(xw, as1, ad1, es, ed);
    gat_aggregate<HH, C1V><<<NN, 256>>>(xw, es, ed, off, csr, b1, agg);
    ln_elu<<<NN, 256>>>(agg, g1, bt1, hb);

    // ---- Layer 2 ----
    gemm_tc<<<g1d, 256, SM_BYTES>>>(hb, W2, xw, NN, HIDV, HIDV);
    attn_scores<HH, C1V><<<NN, 32 * HH>>>(xw, as2, ad2, es, ed);
    gat_aggregate<HH, C1V><<<NN, 256>>>(xw, es, ed, off, csr, b2, agg);
    ln_elu<<<NN, 256>>>(agg, g2, bt2, hb);

    // ---- Layer 3 ----
    gemm_tc<<<g3d, 256, SM_BYTES>>>(hb, W3, xw, NN, COUTV, HIDV);
    attn_scores<1, COUTV><<<NN, 32>>>(xw, as3, ad3, es, ed);
    gat_aggregate<1, COUTV><<<NN, 256>>>(xw, es, ed, off, csr, b3, out);
}

// round 6
// speedup vs baseline: 2.0397x; 1.1665x over previous
#include <cuda_runtime.h>
#include <cuda_bf16.h>
#include <cstdint>

// Problem constants (fixed by the reference)
#define NN    20000
#define DIN   128
#define HH    4
#define C1V   256
#define HIDV  1024
#define COUTV 512
#define EE    160000
#define ETOT  (EE + NN)

// ---------------------------------------------------------------------------
// Scratch (device globals: allocation-free per harness rules)
// ---------------------------------------------------------------------------
__device__ float d_xw [NN * HIDV];   // GEMM output / attention features
__device__ float d_agg[NN * HIDV];   // aggregated messages (pre-LN)
__device__ float d_hb [NN * HIDV];   // post LN+ELU activations
__device__ float d_es [NN * HH];
__device__ float d_ed [NN * HH];
__device__ int   d_cnt[NN];
__device__ int   d_off[NN + 1];
__device__ int   d_cur[NN];
__device__ int   d_csr[ETOT];
__device__ int   d_is64;             // edge_index dtype flag (1 = int64)

// ---------------------------------------------------------------------------
// edge_index dtype detection: int64 values < 20000 have zero odd 32-bit words
// ---------------------------------------------------------------------------
__global__ void detect_dtype(const int* __restrict__ ei32) {
    int all_zero = 1;
    #pragma unroll
    for (int i = 1; i < 64; i += 2)
        if (ei32[i] != 0) all_zero = 0;
    d_is64 = all_zero;
}

__device__ __forceinline__ int edge_at(const void* ei, long long idx) {
    if (d_is64) return (int)((const long long*)ei)[idx];
    return ((const int*)ei)[idx];
}

// ---------------------------------------------------------------------------
// CSR-by-dst construction (counting sort)
// ---------------------------------------------------------------------------
__global__ void count_edges(const void* __restrict__ ei, int* __restrict__ cnt) {
    int e = blockIdx.x * blockDim.x + threadIdx.x;
    if (e >= ETOT) return;
    int d = (e < EE) ? edge_at(ei, (long long)EE + e) : (e - EE);
    atomicAdd(&cnt[d], 1);
}

__global__ void scan_offsets(const int* __restrict__ cnt, int* __restrict__ off,
                             int* __restrict__ cur, int n) {
    __shared__ int sh[1024];
    int carry = 0;
    for (int base = 0; base < n; base += 1024) {
        int i = base + threadIdx.x;
        int v = (i < n) ? cnt[i] : 0;
        sh[threadIdx.x] = v;
        __syncthreads();
        for (int o = 1; o < 1024; o <<= 1) {
            int t = (threadIdx.x >= o) ? sh[threadIdx.x - o] : 0;
            __syncthreads();
            sh[threadIdx.x] += t;
            __syncthreads();
        }
        if (i < n) { int ex = carry + sh[threadIdx.x] - v; off[i] = ex; cur[i] = ex; }
        carry += sh[1023];
        __syncthreads();
    }
    if (threadIdx.x == 0) off[n] = carry;
}

__global__ void scatter_edges(const void* __restrict__ ei,
                              int* __restrict__ cur, int* __restrict__ csr) {
    int e = blockIdx.x * blockDim.x + threadIdx.x;
    if (e >= ETOT) return;
    int s = (e < EE) ? edge_at(ei, e)                  : (e - EE);
    int d = (e < EE) ? edge_at(ei, (long long)EE + e)  : (e - EE);
    int pos = atomicAdd(&cur[d], 1);
    csr[pos] = s;
}

// ---------------------------------------------------------------------------
// Tensor-core GEMM: C[M,N] = A[M,K] @ B[K,N], fp32 via 3-term split-BF16
// mma.sync.m16n8k16. 128x128 block tile, 8 warps (4x2), 32x64 warp tile.
// hi/lo bf16 split precomputed at smem-store time.
// A smem [m][k] bf16, B smem [n][k] bf16 (transposed at store), KPAD=18.
// Requires K%16==0, N%128==0. M guarded.
// ---------------------------------------------------------------------------
#define KPAD 18
#define TILEH (128 * KPAD)                 // halves per [128][KPAD] tile slice
#define SM_HALVES (4 * 2 * TILEH)          // 4 arrays x 2 buffers
#define SM_BYTES  (SM_HALVES * 2)          // 36864

__device__ __forceinline__ void split_bf16(float x, __nv_bfloat16& hi, __nv_bfloat16& lo) {
    hi = __float2bfloat16(x);
    lo = __float2bfloat16(x - __bfloat162float(hi));
}
__device__ __forceinline__ void mma_bf16(float* d, const unsigned* a, const unsigned* b) {
    asm volatile(
        "mma.sync.aligned.m16n8k16.row.col.f32.bf16.bf16.f32 "
        "{%0,%1,%2,%3}, {%4,%5,%6,%7}, {%8,%9}, {%0,%1,%2,%3};"
        : "+f"(d[0]), "+f"(d[1]), "+f"(d[2]), "+f"(d[3])
        : "r"(a[0]), "r"(a[1]), "r"(a[2]), "r"(a[3]), "r"(b[0]), "r"(b[1]));
}

__global__ __launch_bounds__(256, 2) void gemm_tc(const float* __restrict__ A,
                                                  const float* __restrict__ B,
                                                  float* __restrict__ C,
                                                  int M, int N, int K) {
    extern __shared__ __nv_bfloat16 sm[];
    __nv_bfloat16* AH = sm;                // [2][128][KPAD]  A hi  (row = m)
    __nv_bfloat16* AL = sm + 2 * TILEH;    // A lo
    __nv_bfloat16* BH = sm + 4 * TILEH;    // B hi  (row = n, cols = k)
    __nv_bfloat16* BL = sm + 6 * TILEH;    // B lo

    const int tid  = threadIdx.x;
    const int warp = tid >> 5, lane = tid & 31;
    const int g = lane >> 2, t = lane & 3;
    const int wm = (warp & 3) * 32;        // warp row offset in tile
    const int wn = (warp >> 2) * 64;       // warp col offset in tile
    const int m0 = blockIdx.x * 128, n0 = blockIdx.y * 128;

    // Global loader coords
    const int ar0 = tid >> 2, ar1 = ar0 + 64;   // A rows within tile
    const int ak  = (tid & 3) * 4;              // A k offset
    const int bk0 = tid >> 5, bk1 = bk0 + 8;    // B k rows
    const int bn  = (tid & 31) * 4;             // B n offset
    const int gm_a0 = m0 + ar0, gm_a1 = m0 + ar1;
    const int nt_tiles = K / 16;

    float4 av0, av1, bv0, bv1;
    const float4 z4 = make_float4(0.f, 0.f, 0.f, 0.f);

    // Store helpers: split to bf16 hi/lo at store time.
    auto storeA = [&](int buf, const float4& v, int row) {
        const float vv[4] = {v.x, v.y, v.z, v.w};
        int base = (buf * 128 + row) * KPAD + ak;
        __nv_bfloat16 h[4], l[4];
        #pragma unroll
        for (int i = 0; i < 4; i++) split_bf16(vv[i], h[i], l[i]);
        *(__nv_bfloat162*)&AH[base]     = __nv_bfloat162(h[0], h[1]);
        *(__nv_bfloat162*)&AH[base + 2] = __nv_bfloat162(h[2], h[3]);
        *(__nv_bfloat162*)&AL[base]     = __nv_bfloat162(l[0], l[1]);
        *(__nv_bfloat162*)&AL[base + 2] = __nv_bfloat162(l[2], l[3]);
    };
    auto storeB = [&](int buf, const float4& v, int krow) {
        const float vv[4] = {v.x, v.y, v.z, v.w};
        #pragma unroll
        for (int i = 0; i < 4; i++) {
            __nv_bfloat16 h, l;
            split_bf16(vv[i], h, l);
            int idx = (buf * 128 + bn + i) * KPAD + krow;  // transpose
            BH[idx] = h;
            BL[idx] = l;
        }
    };

    // Prefetch + store tile 0
    av0 = (gm_a0 < M) ? *(const float4*)&A[(size_t)gm_a0 * K + ak] : z4;
    av1 = (gm_a1 < M) ? *(const float4*)&A[(size_t)gm_a1 * K + ak] : z4;
    bv0 = *(const float4*)&B[(size_t)bk0 * N + n0 + bn];
    bv1 = *(const float4*)&B[(size_t)bk1 * N + n0 + bn];
    storeA(0, av0, ar0); storeA(0, av1, ar1);
    storeB(0, bv0, bk0); storeB(0, bv1, bk1);
    __syncthreads();

    float acc[2][8][4] = {};
    int buf = 0;
    for (int kt = 0; kt < nt_tiles; kt++) {
        if (kt + 1 < nt_tiles) {
            int k0 = (kt + 1) * 16;
            av0 = (gm_a0 < M) ? *(const float4*)&A[(size_t)gm_a0 * K + k0 + ak] : z4;
            av1 = (gm_a1 < M) ? *(const float4*)&A[(size_t)gm_a1 * K + k0 + ak] : z4;
            bv0 = *(const float4*)&B[(size_t)(k0 + bk0) * N + n0 + bn];
            bv1 = *(const float4*)&B[(size_t)(k0 + bk1) * N + n0 + bn];
        }
        // A fragments: a0=(g,2t) a1=(g+8,2t) a2=(g,2t+8) a3=(g+8,2t+8)
        unsigned ahi[2][4], alo[2][4];
        #pragma unroll
        for (int mt = 0; mt < 2; mt++) {
            int r0 = (buf * 128 + wm + mt * 16 + g) * KPAD;
            int r1 = r0 + 8 * KPAD;
            ahi[mt][0] = *(const unsigned*)&AH[r0 + 2 * t];
            ahi[mt][1] = *(const unsigned*)&AH[r1 + 2 * t];
            ahi[mt][2] = *(const unsigned*)&AH[r0 + 2 * t + 8];
            ahi[mt][3] = *(const unsigned*)&AH[r1 + 2 * t + 8];
            alo[mt][0] = *(const unsigned*)&AL[r0 + 2 * t];
            alo[mt][1] = *(const unsigned*)&AL[r1 + 2 * t];
            alo[mt][2] = *(const unsigned*)&AL[r0 + 2 * t + 8];
            alo[mt][3] = *(const unsigned*)&AL[r1 + 2 * t + 8];
        }
        // B fragments per nt: b0=(2t..2t+1, g) b1=(2t+8..2t+9, g), rows = n
        #pragma unroll
        for (int nt = 0; nt < 8; nt++) {
            int rb = (buf * 128 + wn + nt * 8 + g) * KPAD;
            unsigned bh[2], bl[2];
            bh[0] = *(const unsigned*)&BH[rb + 2 * t];
            bh[1] = *(const unsigned*)&BH[rb + 2 * t + 8];
            bl[0] = *(const unsigned*)&BL[rb + 2 * t];
            bl[1] = *(const unsigned*)&BL[rb + 2 * t + 8];
            mma_bf16(acc[0][nt], ahi[0], bh);
            mma_bf16(acc[1][nt], ahi[1], bh);
            mma_bf16(acc[0][nt], ahi[0], bl);
            mma_bf16(acc[1][nt], ahi[1], bl);
            mma_bf16(acc[0][nt], alo[0], bh);
            mma_bf16(acc[1][nt], alo[1], bh);
        }
        if (kt + 1 < nt_tiles) {
            int nb = buf ^ 1;
            storeA(nb, av0, ar0); storeA(nb, av1, ar1);
            storeB(nb, bv0, bk0); storeB(nb, bv1, bk1);
        }
        __syncthreads();
        buf ^= 1;
    }

    // Epilogue: c0,c1 = (row g, cols 2t,2t+1); c2,c3 = row g+8
    #pragma unroll
    for (int mt = 0; mt < 2; mt++) {
        #pragma unroll
        for (int nt = 0; nt < 8; nt++) {
            const float* dd = acc[mt][nt];
            int m = m0 + wm + mt * 16 + g;
            int n = n0 + wn + nt * 8 + 2 * t;
            if (m < M)
                *(float2*)&C[(size_t)m * N + n] = make_float2(dd[0], dd[1]);
            if (m + 8 < M)
                *(float2*)&C[(size_t)(m + 8) * N + n] = make_float2(dd[2], dd[3]);
        }
    }
}

// ---------------------------------------------------------------------------
// Per-node attention scores: es[n,h] = <xw[n,h,:], a_src[h,:]>, ed likewise
// ---------------------------------------------------------------------------
template<int H, int C>
__global__ void attn_scores(const float* __restrict__ xw,
                            const float* __restrict__ asrc,
                            const float* __restrict__ adst,
                            float* __restrict__ es, float* __restrict__ ed) {
    int n = blockIdx.x;
    int w = threadIdx.x >> 5, lane = threadIdx.x & 31;
    const float* row = xw + (size_t)n * H * C + w * C;
    float ss = 0.f, sd = 0.f;
    for (int c = lane; c < C; c += 32) {
        float v = row[c];
        ss += v * asrc[w * C + c];
        sd += v * adst[w * C + c];
    }
    #pragma unroll
    for (int o = 16; o; o >>= 1) {
        ss += __shfl_down_sync(0xffffffffu, ss, o);
        sd += __shfl_down_sync(0xffffffffu, sd, o);
    }
    if (!lane) { es[n * H + w] = ss; ed[n * H + w] = sd; }
}

// ---------------------------------------------------------------------------
// GAT aggregation: one block per dst node, segment softmax + weighted gather.
// ---------------------------------------------------------------------------
template<int H, int C>
__global__ __launch_bounds__(256) void gat_aggregate(
        const float* __restrict__ xw, const float* __restrict__ es,
        const float* __restrict__ ed, const int* __restrict__ off,
        const int* __restrict__ csr, const float* __restrict__ bias,
        float* __restrict__ out) {
    constexpr int HC = H * C;
    constexpr int F  = HC / 256;
    int n = blockIdx.x, tid = threadIdx.x;
    __shared__ float ed_sh[H], mx_sh[H], id_sh[H], red[256];
    __shared__ float alpha_sh[64 * H];
    __shared__ int   src_sh[64];
    if (tid < H) ed_sh[tid] = ed[n * H + tid];
    __syncthreads();
    int start = off[n];
    int deg   = off[n + 1] - start;   // >= 1 always (self loop)

    // Phase A: max per head
    float lmax[H];
    #pragma unroll
    for (int h = 0; h < H; h++) lmax[h] = -3.4e38f;
    for (int i = tid; i < deg; i += 256) {
        int s = csr[start + i];
        #pragma unroll
        for (int h = 0; h < H; h++) {
            float e = es[s * H + h] + ed_sh[h];
            e = (e > 0.f) ? e : 0.2f * e;
            lmax[h] = fmaxf(lmax[h], e);
        }
    }
    #pragma unroll
    for (int h = 0; h < H; h++) {
        red[tid] = lmax[h]; __syncthreads();
        for (int o = 128; o; o >>= 1) {
            if (tid < o) red[tid] = fmaxf(red[tid], red[tid + o]);
            __syncthreads();
        }
        if (!tid) mx_sh[h] = red[0];
        __syncthreads();
    }

    // Phase B: denominator per head
    float lsum[H];
    #pragma unroll
    for (int h = 0; h < H; h++) lsum[h] = 0.f;
    for (int i = tid; i < deg; i += 256) {
        int s = csr[start + i];
        #pragma unroll
        for (int h = 0; h < H; h++) {
            float e = es[s * H + h] + ed_sh[h];
            e = (e > 0.f) ? e : 0.2f * e;
            lsum[h] += expf(e - mx_sh[h]);
        }
    }
    #pragma unroll
    for (int h = 0; h < H; h++) {
        red[tid] = lsum[h]; __syncthreads();
        for (int o = 128; o; o >>= 1) {
            if (tid < o) red[tid] += red[tid + o];
            __syncthreads();
        }
        if (!tid) id_sh[h] = 1.f / (red[0] + 1e-16f);
        __syncthreads();
    }

    // Phase C: weighted feature accumulation, chunks of 64 edges
    float acc[F];
    #pragma unroll
    for (int k = 0; k < F; k++) acc[k] = 0.f;
    const int head = (tid * F) / C;
    for (int c0 = 0; c0 < deg; c0 += 64) {
        int nc = min(64, deg - c0);
        if (tid < nc * H) {
            int j = tid / H, h = tid - j * H;
            int s = csr[start + c0 + j];
            if (h == 0) src_sh[j] = s;
            float e = es[s * H + h] + ed_sh[h];
            e = (e > 0.f) ? e : 0.2f * e;
            alpha_sh[j * H + h] = expf(e - mx_sh[h]) * id_sh[h];
        }
        __syncthreads();
        for (int j = 0; j < nc; j++) {
            int s = src_sh[j];
            float a = alpha_sh[j * H + head];
            const float* row = xw + (size_t)s * HC + tid * F;
            if constexpr (F == 4) {
                float4 v = *reinterpret_cast<const float4*>(row);
                acc[0] = fmaf(a, v.x, acc[0]); acc[1] = fmaf(a, v.y, acc[1]);
                acc[2] = fmaf(a, v.z, acc[2]); acc[3] = fmaf(a, v.w, acc[3]);
            } else {
                float2 v = *reinterpret_cast<const float2*>(row);
                acc[0] = fmaf(a, v.x, acc[0]); acc[1] = fmaf(a, v.y, acc[1]);
            }
        }
        __syncthreads();
    }
    float* o = out + (size_t)n * HC + tid * F;
    #pragma unroll
    for (int k = 0; k < F; k++) o[k] = acc[k] + bias[tid * F + k];
}

// ---------------------------------------------------------------------------
// Fused LayerNorm + ELU over rows of width 1024 (input already has GAT bias)
// ---------------------------------------------------------------------------
__global__ __launch_bounds__(256) void ln_elu(const float* __restrict__ in,
                                              const float* __restrict__ g,
                                              const float* __restrict__ b,
                                              float* __restrict__ out) {
    int n = blockIdx.x, tid = threadIdx.x;
    const float4 v = *reinterpret_cast<const float4*>(in + (size_t)n * 1024 + tid * 4);
    float s  = v.x + v.y + v.z + v.w;
    float sq = v.x * v.x + v.y * v.y + v.z * v.z + v.w * v.w;
    __shared__ float r1[256], r2[256];
    r1[tid] = s; r2[tid] = sq; __syncthreads();
    for (int o = 128; o; o >>= 1) {
        if (tid < o) { r1[tid] += r1[tid + o]; r2[tid] += r2[tid + o]; }
        __syncthreads();
    }
    float mean = r1[0] * (1.f / 1024.f);
    float var  = r2[0] * (1.f / 1024.f) - mean * mean;
    float rstd = rsqrtf(var + 1e-5f);
    const float4 gv = *reinterpret_cast<const float4*>(g + tid * 4);
    const float4 bv = *reinterpret_cast<const float4*>(b + tid * 4);
    float xin[4] = {v.x, v.y, v.z, v.w};
    float gg[4]  = {gv.x, gv.y, gv.z, gv.w};
    float bb[4]  = {bv.x, bv.y, bv.z, bv.w};
    float4 r;
    float* rp = &r.x;
    #pragma unroll
    for (int k = 0; k < 4; k++) {
        float y = (xin[k] - mean) * rstd * gg[k] + bb[k];
        rp[k] = (y > 0.f) ? y : expm1f(y);
    }
    *reinterpret_cast<float4*>(out + (size_t)n * 1024 + tid * 4) = r;
}

// ---------------------------------------------------------------------------
// Launch
// ---------------------------------------------------------------------------
extern "C" void kernel_launch(void* const* d_in, const int* in_sizes, int n_in,
                              void* d_out, int out_size) {
    const float* x   = (const float*)d_in[0];
    const void*  ei  = d_in[1];                 // int32 or int64 (detected)
    const float* W1  = (const float*)d_in[2];
    const float* as1 = (const float*)d_in[3];
    const float* ad1 = (const float*)d_in[4];
    const float* b1  = (const float*)d_in[5];
    const float* g1  = (const float*)d_in[6];
    const float* bt1 = (const float*)d_in[7];
    const float* W2  = (const float*)d_in[8];
    const float* as2 = (const float*)d_in[9];
    const float* ad2 = (const float*)d_in[10];
    const float* b2  = (const float*)d_in[11];
    const float* g2  = (const float*)d_in[12];
    const float* bt2 = (const float*)d_in[13];
    const float* W3  = (const float*)d_in[14];
    const float* as3 = (const float*)d_in[15];
    const float* ad3 = (const float*)d_in[16];
    const float* b3  = (const float*)d_in[17];
    float* out = (float*)d_out;

    float *xw, *agg, *hb, *es, *ed;
    int *cnt, *off, *cur, *csr;
    cudaGetSymbolAddress((void**)&xw,  d_xw);
    cudaGetSymbolAddress((void**)&agg, d_agg);
    cudaGetSymbolAddress((void**)&hb,  d_hb);
    cudaGetSymbolAddress((void**)&es,  d_es);
    cudaGetSymbolAddress((void**)&ed,  d_ed);
    cudaGetSymbolAddress((void**)&cnt, d_cnt);
    cudaGetSymbolAddress((void**)&off, d_off);
    cudaGetSymbolAddress((void**)&cur, d_cur);
    cudaGetSymbolAddress((void**)&csr, d_csr);

    static int smem_set = 0;
    if (!smem_set) {
        cudaFuncSetAttribute(gemm_tc, cudaFuncAttributeMaxDynamicSharedMemorySize,
                             SM_BYTES);
        smem_set = 1;
    }

    dim3 g1d((NN + 127) / 128, HIDV / 128);
    dim3 g3d((NN + 127) / 128, COUTV / 128);

    // CSR build interleaved with layer-1 GEMM so gemm_tc lands in the ncu
    // profiling slot (launch #5). scatter completes before gat_aggregate.
    detect_dtype<<<1, 1>>>((const int*)ei);
    cudaMemsetAsync(cnt, 0, NN * sizeof(int));
    count_edges<<<(ETOT + 255) / 256, 256>>>(ei, cnt);
    scan_offsets<<<1, 1024>>>(cnt, off, cur, NN);

    // ---- Layer 1 ----
    gemm_tc<<<g1d, 256, SM_BYTES>>>(x, W1, xw, NN, HIDV, DIN);
    scatter_edges<<<(ETOT + 255) / 256, 256>>>(ei, cur, csr);
    attn_scores<HH, C1V><<<NN, 32 * HH>>>(xw, as1, ad1, es, ed);
    gat_aggregate<HH, C1V><<<NN, 256>>>(xw, es, ed, off, csr, b1, agg);
    ln_elu<<<NN, 256>>>(agg, g1, bt1, hb);

    // ---- Layer 2 ----
    gemm_tc<<<g1d, 256, SM_BYTES>>>(hb, W2, xw, NN, HIDV, HIDV);
    attn_scores<HH, C1V><<<NN, 32 * HH>>>(xw, as2, ad2, es, ed);
    gat_aggregate<HH, C1V><<<NN, 256>>>(xw, es, ed, off, csr, b2, agg);
    ln_elu<<<NN, 256>>>(agg, g2, bt2, hb);

    // ---- Layer 3 ----
    gemm_tc<<<g3d, 256, SM_BYTES>>>(hb, W3, xw, NN, COUTV, HIDV);
    attn_scores<1, COUTV><<<NN, 32>>>(xw, as3, ad3, es, ed);
    gat_aggregate<1, COUTV><<<NN, 256>>>(xw, es, ed, off, csr, b3, out);
}

// round 8
// speedup vs baseline: 2.5777x; 1.2638x over previous
#include <cuda_runtime.h>
#include <cuda_bf16.h>
#include <cstdint>

// Problem constants (fixed by the reference)
#define NN    20000
#define DIN   128
#define HH    4
#define C1V   256
#define HIDV  1024
#define COUTV 512
#define EE    160000
#define ETOT  (EE + NN)

// ---------------------------------------------------------------------------
// Scratch (device globals: allocation-free per harness rules)
// ---------------------------------------------------------------------------
__device__ float d_xw [NN * HIDV];          // GEMM output / attention features
__device__ float d_agg[NN * HIDV];          // aggregated messages (pre-LN)
__device__ __nv_bfloat16 d_ah[NN * HIDV];   // A hi (bf16 split activations)
__device__ __nv_bfloat16 d_al[NN * HIDV];   // A lo
__device__ __nv_bfloat16 d_wh[HIDV * HIDV]; // W hi, transposed [N][K]
__device__ __nv_bfloat16 d_wl[HIDV * HIDV]; // W lo
__device__ float d_es [NN * HH];
__device__ float d_ed [NN * HH];
__device__ int   d_cnt[NN];
__device__ int   d_off[NN + 1];
__device__ int   d_cur[NN];
__device__ int   d_csr[ETOT];
__device__ int   d_is64;

// ---------------------------------------------------------------------------
// Helpers
// ---------------------------------------------------------------------------
__device__ __forceinline__ uint32_t smem_u32(const void* p) {
    uint32_t a;
    asm("{ .reg .u64 t; cvta.to.shared.u64 t, %1; cvt.u32.u64 %0, t; }"
        : "=r"(a) : "l"(p));
    return a;
}
__device__ __forceinline__ void split_bf16(float x, __nv_bfloat16& hi, __nv_bfloat16& lo) {
    hi = __float2bfloat16(x);
    lo = __float2bfloat16(x - __bfloat162float(hi));
}
__device__ __forceinline__ void mma_bf16(float* d, const unsigned* a, const unsigned* b) {
    asm volatile(
        "mma.sync.aligned.m16n8k16.row.col.f32.bf16.bf16.f32 "
        "{%0,%1,%2,%3}, {%4,%5,%6,%7}, {%8,%9}, {%0,%1,%2,%3};"
        : "+f"(d[0]), "+f"(d[1]), "+f"(d[2]), "+f"(d[3])
        : "r"(a[0]), "r"(a[1]), "r"(a[2]), "r"(a[3]), "r"(b[0]), "r"(b[1]));
}
#define LDSM4(r, addr)                                                        \
    asm volatile("ldmatrix.sync.aligned.m8n8.x4.shared.b16 {%0,%1,%2,%3}, [%4];" \
                 : "=r"((r)[0]), "=r"((r)[1]), "=r"((r)[2]), "=r"((r)[3])     \
                 : "r"(addr))
__device__ __forceinline__ void cpasync16(uint32_t s, const void* g, int sz) {
    asm volatile("cp.async.ca.shared.global [%0], [%1], 16, %2;"
                 :: "r"(s), "l"(g), "r"(sz) : "memory");
}
#define CP_COMMIT() asm volatile("cp.async.commit_group;" ::: "memory")
#define CP_WAIT1()  asm volatile("cp.async.wait_group 1;" ::: "memory")
#define CP_WAIT0()  asm volatile("cp.async.wait_group 0;" ::: "memory")

// ---------------------------------------------------------------------------
// edge_index dtype detection
// ---------------------------------------------------------------------------
__global__ void detect_dtype(const int* __restrict__ ei32) {
    int all_zero = 1;
    #pragma unroll
    for (int i = 1; i < 64; i += 2)
        if (ei32[i] != 0) all_zero = 0;
    d_is64 = all_zero;
}
__device__ __forceinline__ int edge_at(const void* ei, long long idx) {
    if (d_is64) return (int)((const long long*)ei)[idx];
    return ((const int*)ei)[idx];
}

// ---------------------------------------------------------------------------
// CSR-by-dst construction (counting sort)
// ---------------------------------------------------------------------------
__global__ void count_edges(const void* __restrict__ ei, int* __restrict__ cnt) {
    int e = blockIdx.x * blockDim.x + threadIdx.x;
    if (e >= ETOT) return;
    int d = (e < EE) ? edge_at(ei, (long long)EE + e) : (e - EE);
    atomicAdd(&cnt[d], 1);
}
__global__ void scan_offsets(const int* __restrict__ cnt, int* __restrict__ off,
                             int* __restrict__ cur, int n) {
    __shared__ int sh[1024];
    int carry = 0;
    for (int base = 0; base < n; base += 1024) {
        int i = base + threadIdx.x;
        int v = (i < n) ? cnt[i] : 0;
        sh[threadIdx.x] = v;
        __syncthreads();
        for (int o = 1; o < 1024; o <<= 1) {
            int t = (threadIdx.x >= o) ? sh[threadIdx.x - o] : 0;
            __syncthreads();
            sh[threadIdx.x] += t;
            __syncthreads();
        }
        if (i < n) { int ex = carry + sh[threadIdx.x] - v; off[i] = ex; cur[i] = ex; }
        carry += sh[1023];
        __syncthreads();
    }
    if (threadIdx.x == 0) off[n] = carry;
}
__global__ void scatter_edges(const void* __restrict__ ei,
                              int* __restrict__ cur, int* __restrict__ csr) {
    int e = blockIdx.x * blockDim.x + threadIdx.x;
    if (e >= ETOT) return;
    int s = (e < EE) ? edge_at(ei, e)                  : (e - EE);
    int d = (e < EE) ? edge_at(ei, (long long)EE + e)  : (e - EE);
    int pos = atomicAdd(&cur[d], 1);
    csr[pos] = s;
}

// ---------------------------------------------------------------------------
// prep_x: split fp32 [R,C] into bf16 hi/lo (same layout)
// ---------------------------------------------------------------------------
__global__ void prep_x(const float* __restrict__ in, __nv_bfloat16* __restrict__ H,
                       __nv_bfloat16* __restrict__ L, long long n4) {
    long long i = (long long)blockIdx.x * blockDim.x + threadIdx.x;
    if (i >= n4) return;
    float4 v = ((const float4*)in)[i];
    const float vv[4] = {v.x, v.y, v.z, v.w};
    __nv_bfloat16 h[4], l[4];
    #pragma unroll
    for (int k = 0; k < 4; k++) split_bf16(vv[k], h[k], l[k]);
    ((__nv_bfloat162*)H)[i * 2]     = __nv_bfloat162(h[0], h[1]);
    ((__nv_bfloat162*)H)[i * 2 + 1] = __nv_bfloat162(h[2], h[3]);
    ((__nv_bfloat162*)L)[i * 2]     = __nv_bfloat162(l[0], l[1]);
    ((__nv_bfloat162*)L)[i * 2 + 1] = __nv_bfloat162(l[2], l[3]);
}

// ---------------------------------------------------------------------------
// prep_w: W [K,N] fp32 -> WH, WL [N,K] bf16 (tiled transpose + split)
// ---------------------------------------------------------------------------
__global__ void prep_w(const float* __restrict__ W, __nv_bfloat16* __restrict__ WH,
                       __nv_bfloat16* __restrict__ WL, int K, int N) {
    __shared__ float tile[32][33];
    int bk = blockIdx.x * 32, bn = blockIdx.y * 32;
    int tx = threadIdx.x, ty = threadIdx.y;   // 32 x 8
    #pragma unroll
    for (int j = ty; j < 32; j += 8)
        tile[j][tx] = W[(size_t)(bk + j) * N + bn + tx];
    __syncthreads();
    #pragma unroll
    for (int j = ty; j < 32; j += 8) {
        float v = tile[tx][j];
        __nv_bfloat16 h, l;
        split_bf16(v, h, l);
        WH[(size_t)(bn + j) * K + bk + tx] = h;
        WL[(size_t)(bn + j) * K + bk + tx] = l;
    }
}

// ---------------------------------------------------------------------------
// GEMM: C[M,N] = A[M,K] @ W^T, A/W pre-split bf16 hi/lo, W is [N,K].
// fp32 accuracy via 3-term split: AH*WH + AH*WL + AL*WH.
// mma.sync.m16n8k16.bf16, ldmatrix fragment loads, cp.async double buffer.
// 128x128 CTA tile, BK=32, 8 warps (4x2), 32x64 warp tile.
// ---------------------------------------------------------------------------
#define BK 32
#define BSTR 40                         // halves per smem row (80B, LDSM conflict-free)
#define SLICE_B (128 * BSTR * 2)        // 10240 bytes per [128][40] tile
#define GSM_BYTES (8 * SLICE_B)         // 4 arrays x 2 buffers = 81920

__global__ __launch_bounds__(256, 2) void gemm_tc(
        const __nv_bfloat16* __restrict__ AHg, const __nv_bfloat16* __restrict__ ALg,
        const __nv_bfloat16* __restrict__ WHg, const __nv_bfloat16* __restrict__ WLg,
        float* __restrict__ C, int M, int N, int K) {
    extern __shared__ char smem[];
    const uint32_t sbase = smem_u32(smem);
    const int tid = threadIdx.x;
    const int warp = tid >> 5, lane = tid & 31;
    const int g = lane >> 2, t = lane & 3;
    const int wm = (warp & 3) * 32;
    const int wn = (warp >> 2) * 64;
    const int m0 = blockIdx.x * 128, n0 = blockIdx.y * 128;
    const int NT = K / BK;

    // array bases: arr 0=AH 1=AL 2=BH 3=BL ; each arr has 2 buffers
    auto abase = [&](int arr, int buf) -> uint32_t {
        return sbase + (uint32_t)(arr * 2 + buf) * SLICE_B;
    };

    // LDSM lane addressing (precomputed row/k offsets)
    const int a_row0 = wm + ((lane >> 3) & 1) * 8 + (lane & 7);       // mt=0
    const int a_koff = ((lane >> 4) & 1) * 8;
    const int b_rowb = wn + ((lane >> 4) & 1) * 8 + (lane & 7);       // + ntp*16
    const int b_koff = ((lane >> 3) & 1) * 8;

    // cp.async loader: 512 uint4 per array tile; 2 per thread per array
    auto load_tile = [&](int buf, int k0) {
        #pragma unroll
        for (int it = 0; it < 2; it++) {
            int idx = it * 256 + tid;
            int row = idx >> 2, q = idx & 3;
            uint32_t soff = (uint32_t)(row * BSTR + q * 8) * 2;
            int gm = m0 + row;
            int gmc = (gm < M) ? gm : (M - 1);
            int sz = (gm < M) ? 16 : 0;
            cpasync16(abase(0, buf) + soff, AHg + (size_t)gmc * K + k0 + q * 8, sz);
            cpasync16(abase(1, buf) + soff, ALg + (size_t)gmc * K + k0 + q * 8, sz);
            int gn = n0 + row;   // N multiple of 128 -> always valid
            cpasync16(abase(2, buf) + soff, WHg + (size_t)gn * K + k0 + q * 8, 16);
            cpasync16(abase(3, buf) + soff, WLg + (size_t)gn * K + k0 + q * 8, 16);
        }
    };

    load_tile(0, 0);
    CP_COMMIT();

    float acc[2][8][4] = {};
    for (int kt = 0; kt < NT; kt++) {
        int buf = kt & 1;
        if (kt + 1 < NT) {
            load_tile(buf ^ 1, (kt + 1) * BK);
            CP_COMMIT();
            CP_WAIT1();
        } else {
            CP_WAIT0();
        }
        __syncthreads();

        #pragma unroll
        for (int kb = 0; kb < BK; kb += 16) {
            unsigned ahi[2][4], alo[2][4];
            #pragma unroll
            for (int mt = 0; mt < 2; mt++) {
                uint32_t aoff = (uint32_t)((a_row0 + mt * 16) * BSTR + kb + a_koff) * 2;
                LDSM4(ahi[mt], abase(0, buf) + aoff);
                LDSM4(alo[mt], abase(1, buf) + aoff);
            }
            #pragma unroll
            for (int ntp = 0; ntp < 4; ntp++) {
                unsigned bh[4], bl[4];
                uint32_t boff = (uint32_t)((b_rowb + ntp * 16) * BSTR + kb + b_koff) * 2;
                LDSM4(bh, abase(2, buf) + boff);
                LDSM4(bl, abase(3, buf) + boff);
                #pragma unroll
                for (int sub = 0; sub < 2; sub++) {
                    int nt = ntp * 2 + sub;
                    const unsigned* bhp = bh + sub * 2;
                    const unsigned* blp = bl + sub * 2;
                    mma_bf16(acc[0][nt], ahi[0], bhp);
                    mma_bf16(acc[1][nt], ahi[1], bhp);
                    mma_bf16(acc[0][nt], ahi[0], blp);
                    mma_bf16(acc[1][nt], ahi[1], blp);
                    mma_bf16(acc[0][nt], alo[0], bhp);
                    mma_bf16(acc[1][nt], alo[1], bhp);
                }
            }
        }
        __syncthreads();
    }

    // Epilogue: c0,c1 = (row g, cols 2t,2t+1); c2,c3 = row g+8
    #pragma unroll
    for (int mt = 0; mt < 2; mt++) {
        #pragma unroll
        for (int nt = 0; nt < 8; nt++) {
            const float* dd = acc[mt][nt];
            int m = m0 + wm + mt * 16 + g;
            int n = n0 + wn + nt * 8 + 2 * t;
            if (m < M)
                *(float2*)&C[(size_t)m * N + n] = make_float2(dd[0], dd[1]);
            if (m + 8 < M)
                *(float2*)&C[(size_t)(m + 8) * N + n] = make_float2(dd[2], dd[3]);
        }
    }
}

// ---------------------------------------------------------------------------
// Per-node attention scores
// ---------------------------------------------------------------------------
template<int H, int C>
__global__ void attn_scores(const float* __restrict__ xw,
                            const float* __restrict__ asrc,
                            const float* __restrict__ adst,
                            float* __restrict__ es, float* __restrict__ ed) {
    int n = blockIdx.x;
    int w = threadIdx.x >> 5, lane = threadIdx.x & 31;
    const float* row = xw + (size_t)n * H * C + w * C;
    float ss = 0.f, sd = 0.f;
    for (int c = lane; c < C; c += 32) {
        float v = row[c];
        ss += v * asrc[w * C + c];
        sd += v * adst[w * C + c];
    }
    #pragma unroll
    for (int o = 16; o; o >>= 1) {
        ss += __shfl_down_sync(0xffffffffu, ss, o);
        sd += __shfl_down_sync(0xffffffffu, sd, o);
    }
    if (!lane) { es[n * H + w] = ss; ed[n * H + w] = sd; }
}

// ---------------------------------------------------------------------------
// GAT aggregation
// ---------------------------------------------------------------------------
template<int H, int C>
__global__ __launch_bounds__(256) void gat_aggregate(
        const float* __restrict__ xw, const float* __restrict__ es,
        const float* __restrict__ ed, const int* __restrict__ off,
        const int* __restrict__ csr, const float* __restrict__ bias,
        float* __restrict__ out) {
    constexpr int HC = H * C;
    constexpr int F  = HC / 256;
    int n = blockIdx.x, tid = threadIdx.x;
    __shared__ float ed_sh[H], mx_sh[H], id_sh[H], red[256];
    __shared__ float alpha_sh[64 * H];
    __shared__ int   src_sh[64];
    if (tid < H) ed_sh[tid] = ed[n * H + tid];
    __syncthreads();
    int start = off[n];
    int deg   = off[n + 1] - start;

    float lmax[H];
    #pragma unroll
    for (int h = 0; h < H; h++) lmax[h] = -3.4e38f;
    for (int i = tid; i < deg; i += 256) {
        int s = csr[start + i];
        #pragma unroll
        for (int h = 0; h < H; h++) {
            float e = es[s * H + h] + ed_sh[h];
            e = (e > 0.f) ? e : 0.2f * e;
            lmax[h] = fmaxf(lmax[h], e);
        }
    }
    #pragma unroll
    for (int h = 0; h < H; h++) {
        red[tid] = lmax[h]; __syncthreads();
        for (int o = 128; o; o >>= 1) {
            if (tid < o) red[tid] = fmaxf(red[tid], red[tid + o]);
            __syncthreads();
        }
        if (!tid) mx_sh[h] = red[0];
        __syncthreads();
    }

    float lsum[H];
    #pragma unroll
    for (int h = 0; h < H; h++) lsum[h] = 0.f;
    for (int i = tid; i < deg; i += 256) {
        int s = csr[start + i];
        #pragma unroll
        for (int h = 0; h < H; h++) {
            float e = es[s * H + h] + ed_sh[h];
            e = (e > 0.f) ? e : 0.2f * e;
            lsum[h] += expf(e - mx_sh[h]);
        }
    }
    #pragma unroll
    for (int h = 0; h < H; h++) {
        red[tid] = lsum[h]; __syncthreads();
        for (int o = 128; o; o >>= 1) {
            if (tid < o) red[tid] += red[tid + o];
            __syncthreads();
        }
        if (!tid) id_sh[h] = 1.f / (red[0] + 1e-16f);
        __syncthreads();
    }

    float acc[F];
    #pragma unroll
    for (int k = 0; k < F; k++) acc[k] = 0.f;
    const int head = (tid * F) / C;
    for (int c0 = 0; c0 < deg; c0 += 64) {
        int nc = min(64, deg - c0);
        if (tid < nc * H) {
            int j = tid / H, h = tid - j * H;
            int s = csr[start + c0 + j];
            if (h == 0) src_sh[j] = s;
            float e = es[s * H + h] + ed_sh[h];
            e = (e > 0.f) ? e : 0.2f * e;
            alpha_sh[j * H + h] = expf(e - mx_sh[h]) * id_sh[h];
        }
        __syncthreads();
        for (int j = 0; j < nc; j++) {
            int s = src_sh[j];
            float a = alpha_sh[j * H + head];
            const float* row = xw + (size_t)s * HC + tid * F;
            if constexpr (F == 4) {
                float4 v = *reinterpret_cast<const float4*>(row);
                acc[0] = fmaf(a, v.x, acc[0]); acc[1] = fmaf(a, v.y, acc[1]);
                acc[2] = fmaf(a, v.z, acc[2]); acc[3] = fmaf(a, v.w, acc[3]);
            } else {
                float2 v = *reinterpret_cast<const float2*>(row);
                acc[0] = fmaf(a, v.x, acc[0]); acc[1] = fmaf(a, v.y, acc[1]);
            }
        }
        __syncthreads();
    }
    float* o = out + (size_t)n * HC + tid * F;
    #pragma unroll
    for (int k = 0; k < F; k++) o[k] = acc[k] + bias[tid * F + k];
}

// ---------------------------------------------------------------------------
// Fused LayerNorm + ELU; emits bf16 hi/lo splits (GEMM A operand)
// ---------------------------------------------------------------------------
__global__ __launch_bounds__(256) void ln_elu(const float* __restrict__ in,
                                              const float* __restrict__ g,
                                              const float* __restrict__ b,
                                              __nv_bfloat16* __restrict__ outH,
                                              __nv_bfloat16* __restrict__ outL) {
    int n = blockIdx.x, tid = threadIdx.x;
    const float4 v = *reinterpret_cast<const float4*>(in + (size_t)n * 1024 + tid * 4);
    float s  = v.x + v.y + v.z + v.w;
    float sq = v.x * v.x + v.y * v.y + v.z * v.z + v.w * v.w;
    __shared__ float r1[256], r2[256];
    r1[tid] = s; r2[tid] = sq; __syncthreads();
    for (int o = 128; o; o >>= 1) {
        if (tid < o) { r1[tid] += r1[tid + o]; r2[tid] += r2[tid + o]; }
        __syncthreads();
    }
    float mean = r1[0] * (1.f / 1024.f);
    float var  = r2[0] * (1.f / 1024.f) - mean * mean;
    float rstd = rsqrtf(var + 1e-5f);
    const float4 gv = *reinterpret_cast<const float4*>(g + tid * 4);
    const float4 bv = *reinterpret_cast<const float4*>(b + tid * 4);
    float xin[4] = {v.x, v.y, v.z, v.w};
    float gg[4]  = {gv.x, gv.y, gv.z, gv.w};
    float bb[4]  = {bv.x, bv.y, bv.z, bv.w};
    __nv_bfloat16 h[4], l[4];
    #pragma unroll
    for (int k = 0; k < 4; k++) {
        float y = (xin[k] - mean) * rstd * gg[k] + bb[k];
        y = (y > 0.f) ? y : expm1f(y);
        split_bf16(y, h[k], l[k]);
    }
    size_t o2 = (size_t)n * 512 + tid * 2;
    ((__nv_bfloat162*)outH)[o2]     = __nv_bfloat162(h[0], h[1]);
    ((__nv_bfloat162*)outH)[o2 + 1] = __nv_bfloat162(h[2], h[3]);
    ((__nv_bfloat162*)outL)[o2]     = __nv_bfloat162(l[0], l[1]);
    ((__nv_bfloat162*)outL)[o2 + 1] = __nv_bfloat162(l[2], l[3]);
}

// ---------------------------------------------------------------------------
// Launch
// ---------------------------------------------------------------------------
extern "C" void kernel_launch(void* const* d_in, const int* in_sizes, int n_in,
                              void* d_out, int out_size) {
    const float* x   = (const float*)d_in[0];
    const void*  ei  = d_in[1];
    const float* W1  = (const float*)d_in[2];
    const float* as1 = (const float*)d_in[3];
    const float* ad1 = (const float*)d_in[4];
    const float* b1  = (const float*)d_in[5];
    const float* g1  = (const float*)d_in[6];
    const float* bt1 = (const float*)d_in[7];
    const float* W2  = (const float*)d_in[8];
    const float* as2 = (const float*)d_in[9];
    const float* ad2 = (const float*)d_in[10];
    const float* b2  = (const float*)d_in[11];
    const float* g2  = (const float*)d_in[12];
    const float* bt2 = (const float*)d_in[13];
    const float* W3  = (const float*)d_in[14];
    const float* as3 = (const float*)d_in[15];
    const float* ad3 = (const float*)d_in[16];
    const float* b3  = (const float*)d_in[17];
    float* out = (float*)d_out;

    float *xw, *agg, *es, *ed;
    __nv_bfloat16 *ah, *al, *wh, *wl;
    int *cnt, *off, *cur, *csr;
    cudaGetSymbolAddress((void**)&xw,  d_xw);
    cudaGetSymbolAddress((void**)&agg, d_agg);
    cudaGetSymbolAddress((void**)&ah,  d_ah);
    cudaGetSymbolAddress((void**)&al,  d_al);
    cudaGetSymbolAddress((void**)&wh,  d_wh);
    cudaGetSymbolAddress((void**)&wl,  d_wl);
    cudaGetSymbolAddress((void**)&es,  d_es);
    cudaGetSymbolAddress((void**)&ed,  d_ed);
    cudaGetSymbolAddress((void**)&cnt, d_cnt);
    cudaGetSymbolAddress((void**)&off, d_off);
    cudaGetSymbolAddress((void**)&cur, d_cur);
    cudaGetSymbolAddress((void**)&csr, d_csr);

    static int attr_set = 0;
    if (!attr_set) {
        cudaFuncSetAttribute(gemm_tc, cudaFuncAttributeMaxDynamicSharedMemorySize,
                             GSM_BYTES);
        attr_set = 1;
    }

    dim3 tb(32, 8);

    detect_dtype<<<1, 1>>>((const int*)ei);
    cudaMemsetAsync(cnt, 0, NN * sizeof(int));
    count_edges<<<(ETOT + 255) / 256, 256>>>(ei, cnt);
    scan_offsets<<<1, 1024>>>(cnt, off, cur, NN);

    // ---- Layer 1 ----
    prep_x<<<(NN * DIN / 4 + 255) / 256, 256>>>(x, ah, al, (long long)NN * DIN / 4);
    prep_w<<<dim3(DIN / 32, HIDV / 32), tb>>>(W1, wh, wl, DIN, HIDV);
    gemm_tc<<<dim3((NN + 127) / 128, HIDV / 128), 256, GSM_BYTES>>>(
        ah, al, wh, wl, xw, NN, HIDV, DIN);
    scatter_edges<<<(ETOT + 255) / 256, 256>>>(ei, cur, csr);
    attn_scores<HH, C1V><<<NN, 32 * HH>>>(xw, as1, ad1, es, ed);
    gat_aggregate<HH, C1V><<<NN, 256>>>(xw, es, ed, off, csr, b1, agg);
    ln_elu<<<NN, 256>>>(agg, g1, bt1, ah, al);

    // ---- Layer 2 ----
    prep_w<<<dim3(HIDV / 32, HIDV / 32), tb>>>(W2, wh, wl, HIDV, HIDV);
    gemm_tc<<<dim3((NN + 127) / 128, HIDV / 128), 256, GSM_BYTES>>>(
        ah, al, wh, wl, xw, NN, HIDV, HIDV);
    attn_scores<HH, C1V><<<NN, 32 * HH>>>(xw, as2, ad2, es, ed);
    gat_aggregate<HH, C1V><<<NN, 256>>>(xw, es, ed, off, csr, b2, agg);
    ln_elu<<<NN, 256>>>(agg, g2, bt2, ah, al);

    // ---- Layer 3 ----
    prep_w<<<dim3(HIDV / 32, COUTV / 32), tb>>>(W3, wh, wl, HIDV, COUTV);
    gemm_tc<<<dim3((NN + 127) / 128, COUTV / 128), 256, GSM_BYTES>>>(
        ah, al, wh, wl, xw, NN, COUTV, HIDV);
    attn_scores<1, COUTV><<<NN, 32>>>(xw, as3, ad3, es, ed);
    gat_aggregate<1, COUTV><<<NN, 256>>>(xw, es, ed, off, csr, b3, out);
}

// round 10
// speedup vs baseline: 3.0764x; 1.1935x over previous
#include <cuda_runtime.h>
#include <cuda_bf16.h>
#include <cstdint>

// Problem constants (fixed by the reference)
#define NN    20000
#define DIN   128
#define HH    4
#define C1V   256
#define HIDV  1024
#define COUTV 512
#define EE    160000
#define ETOT  (EE + NN)

// ---------------------------------------------------------------------------
// Scratch (device globals: allocation-free per harness rules)
// ---------------------------------------------------------------------------
__device__ float d_xw [NN * HIDV];          // GEMM output / attention features
__device__ float d_agg[NN * HIDV];          // aggregated messages (pre-LN)
__device__ __nv_bfloat16 d_ah[NN * HIDV];   // A hi (bf16 split activations)
__device__ __nv_bfloat16 d_al[NN * HIDV];   // A lo
__device__ __nv_bfloat16 d_wh[HIDV * HIDV]; // W hi, transposed [N][K]
__device__ __nv_bfloat16 d_wl[HIDV * HIDV]; // W lo
__device__ float d_es [NN * HH];
__device__ float d_ed [NN * HH];
__device__ int   d_cnt[NN];
__device__ int   d_off[NN + 1];
__device__ int   d_cur[NN];
__device__ int   d_csr[ETOT];
__device__ int   d_is64;

// ---------------------------------------------------------------------------
// Helpers
// ---------------------------------------------------------------------------
__device__ __forceinline__ uint32_t smem_u32(const void* p) {
    uint32_t a;
    asm("{ .reg .u64 t; cvta.to.shared.u64 t, %1; cvt.u32.u64 %0, t; }"
        : "=r"(a) : "l"(p));
    return a;
}
__device__ __forceinline__ void split_bf16(float x, __nv_bfloat16& hi, __nv_bfloat16& lo) {
    hi = __float2bfloat16(x);
    lo = __float2bfloat16(x - __bfloat162float(hi));
}
__device__ __forceinline__ void mma_bf16(float* d, const unsigned* a, const unsigned* b) {
    asm volatile(
        "mma.sync.aligned.m16n8k16.row.col.f32.bf16.bf16.f32 "
        "{%0,%1,%2,%3}, {%4,%5,%6,%7}, {%8,%9}, {%0,%1,%2,%3};"
        : "+f"(d[0]), "+f"(d[1]), "+f"(d[2]), "+f"(d[3])
        : "r"(a[0]), "r"(a[1]), "r"(a[2]), "r"(a[3]), "r"(b[0]), "r"(b[1]));
}
#define LDSM4(r, addr)                                                        \
    asm volatile("ldmatrix.sync.aligned.m8n8.x4.shared.b16 {%0,%1,%2,%3}, [%4];" \
                 : "=r"((r)[0]), "=r"((r)[1]), "=r"((r)[2]), "=r"((r)[3])     \
                 : "r"(addr))
__device__ __forceinline__ void cpasync16(uint32_t s, const void* g, int sz) {
    asm volatile("cp.async.ca.shared.global [%0], [%1], 16, %2;"
                 :: "r"(s), "l"(g), "r"(sz) : "memory");
}
#define CP_COMMIT() asm volatile("cp.async.commit_group;" ::: "memory")
#define CP_WAIT1()  asm volatile("cp.async.wait_group 1;" ::: "memory")
#define CP_WAIT0()  asm volatile("cp.async.wait_group 0;" ::: "memory")

// ---------------------------------------------------------------------------
// edge_index dtype detection
// ---------------------------------------------------------------------------
__global__ void detect_dtype(const int* __restrict__ ei32) {
    int all_zero = 1;
    #pragma unroll
    for (int i = 1; i < 64; i += 2)
        if (ei32[i] != 0) all_zero = 0;
    d_is64 = all_zero;
}
__device__ __forceinline__ int edge_at(const void* ei, long long idx) {
    if (d_is64) return (int)((const long long*)ei)[idx];
    return ((const int*)ei)[idx];
}

// ---------------------------------------------------------------------------
// CSR-by-dst construction (counting sort)
// ---------------------------------------------------------------------------
__global__ void count_edges(const void* __restrict__ ei, int* __restrict__ cnt) {
    int e = blockIdx.x * blockDim.x + threadIdx.x;
    if (e >= ETOT) return;
    int d = (e < EE) ? edge_at(ei, (long long)EE + e) : (e - EE);
    atomicAdd(&cnt[d], 1);
}
__global__ void scan_offsets(const int* __restrict__ cnt, int* __restrict__ off,
                             int* __restrict__ cur, int n) {
    __shared__ int sh[1024];
    int carry = 0;
    for (int base = 0; base < n; base += 1024) {
        int i = base + threadIdx.x;
        int v = (i < n) ? cnt[i] : 0;
        sh[threadIdx.x] = v;
        __syncthreads();
        for (int o = 1; o < 1024; o <<= 1) {
            int t = (threadIdx.x >= o) ? sh[threadIdx.x - o] : 0;
            __syncthreads();
            sh[threadIdx.x] += t;
            __syncthreads();
        }
        if (i < n) { int ex = carry + sh[threadIdx.x] - v; off[i] = ex; cur[i] = ex; }
        carry += sh[1023];
        __syncthreads();
    }
    if (threadIdx.x == 0) off[n] = carry;
}
__global__ void scatter_edges(const void* __restrict__ ei,
                              int* __restrict__ cur, int* __restrict__ csr) {
    int e = blockIdx.x * blockDim.x + threadIdx.x;
    if (e >= ETOT) return;
    int s = (e < EE) ? edge_at(ei, e)                  : (e - EE);
    int d = (e < EE) ? edge_at(ei, (long long)EE + e)  : (e - EE);
    int pos = atomicAdd(&cur[d], 1);
    csr[pos] = s;
}

// ---------------------------------------------------------------------------
// prep_x: split fp32 [R,C] into bf16 hi/lo (same layout)
// ---------------------------------------------------------------------------
__global__ void prep_x(const float* __restrict__ in, __nv_bfloat16* __restrict__ H,
                       __nv_bfloat16* __restrict__ L, long long n4) {
    long long i = (long long)blockIdx.x * blockDim.x + threadIdx.x;
    if (i >= n4) return;
    float4 v = ((const float4*)in)[i];
    const float vv[4] = {v.x, v.y, v.z, v.w};
    __nv_bfloat16 h[4], l[4];
    #pragma unroll
    for (int k = 0; k < 4; k++) split_bf16(vv[k], h[k], l[k]);
    ((__nv_bfloat162*)H)[i * 2]     = __nv_bfloat162(h[0], h[1]);
    ((__nv_bfloat162*)H)[i * 2 + 1] = __nv_bfloat162(h[2], h[3]);
    ((__nv_bfloat162*)L)[i * 2]     = __nv_bfloat162(l[0], l[1]);
    ((__nv_bfloat162*)L)[i * 2 + 1] = __nv_bfloat162(l[2], l[3]);
}

// ---------------------------------------------------------------------------
// prep_w: W [K,N] fp32 -> WH, WL [N,K] bf16 (tiled transpose + split)
// ---------------------------------------------------------------------------
__global__ void prep_w(const float* __restrict__ W, __nv_bfloat16* __restrict__ WH,
                       __nv_bfloat16* __restrict__ WL, int K, int N) {
    __shared__ float tile[32][33];
    int bk = blockIdx.x * 32, bn = blockIdx.y * 32;
    int tx = threadIdx.x, ty = threadIdx.y;   // 32 x 8
    #pragma unroll
    for (int j = ty; j < 32; j += 8)
        tile[j][tx] = W[(size_t)(bk + j) * N + bn + tx];
    __syncthreads();
    #pragma unroll
    for (int j = ty; j < 32; j += 8) {
        float v = tile[tx][j];
        __nv_bfloat16 h, l;
        split_bf16(v, h, l);
        WH[(size_t)(bn + j) * K + bk + tx] = h;
        WL[(size_t)(bn + j) * K + bk + tx] = l;
    }
}

// ---------------------------------------------------------------------------
// GEMM: C[M,N] = A[M,K] @ W^T, A/W pre-split bf16 hi/lo, W is [N,K].
// fp32 accuracy via 3-term split: AH*WH + AH*WL + AL*WH.
// mma.sync.m16n8k16.bf16, ldmatrix fragment loads, cp.async double buffer.
// 128x128 CTA tile, BK=32, 8 warps (4x2), 32x64 warp tile.
// ---------------------------------------------------------------------------
#define BK 32
#define BSTR 40                         // halves per smem row (80B, LDSM conflict-free)
#define SLICE_B (128 * BSTR * 2)        // 10240 bytes per [128][40] tile
#define GSM_BYTES (8 * SLICE_B)         // 4 arrays x 2 buffers = 81920

__global__ __launch_bounds__(256, 2) void gemm_tc(
        const __nv_bfloat16* __restrict__ AHg, const __nv_bfloat16* __restrict__ ALg,
        const __nv_bfloat16* __restrict__ WHg, const __nv_bfloat16* __restrict__ WLg,
        float* __restrict__ C, int M, int N, int K) {
    extern __shared__ char smem[];
    const uint32_t sbase = smem_u32(smem);
    const int tid = threadIdx.x;
    const int warp = tid >> 5, lane = tid & 31;
    const int g = lane >> 2, t = lane & 3;
    const int wm = (warp & 3) * 32;
    const int wn = (warp >> 2) * 64;
    const int m0 = blockIdx.x * 128, n0 = blockIdx.y * 128;
    const int NT = K / BK;

    auto abase = [&](int arr, int buf) -> uint32_t {
        return sbase + (uint32_t)(arr * 2 + buf) * SLICE_B;
    };

    const int a_row0 = wm + ((lane >> 3) & 1) * 8 + (lane & 7);
    const int a_koff = ((lane >> 4) & 1) * 8;
    const int b_rowb = wn + ((lane >> 4) & 1) * 8 + (lane & 7);
    const int b_koff = ((lane >> 3) & 1) * 8;

    auto load_tile = [&](int buf, int k0) {
        #pragma unroll
        for (int it = 0; it < 2; it++) {
            int idx = it * 256 + tid;
            int row = idx >> 2, q = idx & 3;
            uint32_t soff = (uint32_t)(row * BSTR + q * 8) * 2;
            int gm = m0 + row;
            int gmc = (gm < M) ? gm : (M - 1);
            int sz = (gm < M) ? 16 : 0;
            cpasync16(abase(0, buf) + soff, AHg + (size_t)gmc * K + k0 + q * 8, sz);
            cpasync16(abase(1, buf) + soff, ALg + (size_t)gmc * K + k0 + q * 8, sz);
            int gn = n0 + row;
            cpasync16(abase(2, buf) + soff, WHg + (size_t)gn * K + k0 + q * 8, 16);
            cpasync16(abase(3, buf) + soff, WLg + (size_t)gn * K + k0 + q * 8, 16);
        }
    };

    load_tile(0, 0);
    CP_COMMIT();

    float acc[2][8][4] = {};
    for (int kt = 0; kt < NT; kt++) {
        int buf = kt & 1;
        if (kt + 1 < NT) {
            load_tile(buf ^ 1, (kt + 1) * BK);
            CP_COMMIT();
            CP_WAIT1();
        } else {
            CP_WAIT0();
        }
        __syncthreads();

        #pragma unroll
        for (int kb = 0; kb < BK; kb += 16) {
            unsigned ahi[2][4], alo[2][4];
            #pragma unroll
            for (int mt = 0; mt < 2; mt++) {
                uint32_t aoff = (uint32_t)((a_row0 + mt * 16) * BSTR + kb + a_koff) * 2;
                LDSM4(ahi[mt], abase(0, buf) + aoff);
                LDSM4(alo[mt], abase(1, buf) + aoff);
            }
            #pragma unroll
            for (int ntp = 0; ntp < 4; ntp++) {
                unsigned bh[4], bl[4];
                uint32_t boff = (uint32_t)((b_rowb + ntp * 16) * BSTR + kb + b_koff) * 2;
                LDSM4(bh, abase(2, buf) + boff);
                LDSM4(bl, abase(3, buf) + boff);
                #pragma unroll
                for (int sub = 0; sub < 2; sub++) {
                    int nt = ntp * 2 + sub;
                    const unsigned* bhp = bh + sub * 2;
                    const unsigned* blp = bl + sub * 2;
                    mma_bf16(acc[0][nt], ahi[0], bhp);
                    mma_bf16(acc[1][nt], ahi[1], bhp);
                    mma_bf16(acc[0][nt], ahi[0], blp);
                    mma_bf16(acc[1][nt], ahi[1], blp);
                    mma_bf16(acc[0][nt], alo[0], bhp);
                    mma_bf16(acc[1][nt], alo[1], bhp);
                }
            }
        }
        __syncthreads();
    }

    #pragma unroll
    for (int mt = 0; mt < 2; mt++) {
        #pragma unroll
        for (int nt = 0; nt < 8; nt++) {
            const float* dd = acc[mt][nt];
            int m = m0 + wm + mt * 16 + g;
            int n = n0 + wn + nt * 8 + 2 * t;
            if (m < M)
                *(float2*)&C[(size_t)m * N + n] = make_float2(dd[0], dd[1]);
            if (m + 8 < M)
                *(float2*)&C[(size_t)(m + 8) * N + n] = make_float2(dd[2], dd[3]);
        }
    }
}

// ---------------------------------------------------------------------------
// Per-node attention scores
// ---------------------------------------------------------------------------
template<int H, int C>
__global__ void attn_scores(const float* __restrict__ xw,
                            const float* __restrict__ asrc,
                            const float* __restrict__ adst,
                            float* __restrict__ es, float* __restrict__ ed) {
    int n = blockIdx.x;
    int w = threadIdx.x >> 5, lane = threadIdx.x & 31;
    const float* row = xw + (size_t)n * H * C + w * C;
    float ss = 0.f, sd = 0.f;
    for (int c = lane; c < C; c += 32) {
        float v = row[c];
        ss += v * asrc[w * C + c];
        sd += v * adst[w * C + c];
    }
    #pragma unroll
    for (int o = 16; o; o >>= 1) {
        ss += __shfl_down_sync(0xffffffffu, ss, o);
        sd += __shfl_down_sync(0xffffffffu, sd, o);
    }
    if (!lane) { es[n * H + w] = ss; ed[n * H + w] = sd; }
}

// ---------------------------------------------------------------------------
// GAT aggregation: one block per dst node.
// Threads map to (edge j, head h): h = tid & (H-1), j = tid / H.
// Softmax max/denominator via warp shuffles at stride H.
// Second-stage reductions run on the FULL first warp (shuffle-mask safe).
// ---------------------------------------------------------------------------
template<int H, int C>
__global__ __launch_bounds__(256) void gat_aggregate(
        const float* __restrict__ xw, const float* __restrict__ es,
        const float* __restrict__ ed, const int* __restrict__ off,
        const int* __restrict__ csr, const float* __restrict__ bias,
        float* __restrict__ out) {
    constexpr int HC = H * C;
    constexpr int F  = HC / 256;
    constexpr int JJ = 256 / H;          // edges per chunk
    int n = blockIdx.x, tid = threadIdx.x;
    int lane = tid & 31, wid = tid >> 5;
    const int h = tid & (H - 1);
    const int j = tid / H;
    __shared__ float ed_sh[H], mx_sh[H], id_sh[H];
    __shared__ float part[8 * H];
    __shared__ float alpha_sh[JJ * H];
    __shared__ int   src_sh[JJ];
    if (tid < H) ed_sh[tid] = ed[n * H + tid];
    __syncthreads();
    int start = off[n];
    int deg   = off[n + 1] - start;      // >= 1 (self loop)
    float edh = ed_sh[h];

    // Pass 1: max per head
    float lmax = -3.4e38f;
    for (int i = j; i < deg; i += JJ) {
        int s = csr[start + i];
        float e = es[s * H + h] + edh;
        e = (e > 0.f) ? e : 0.2f * e;
        lmax = fmaxf(lmax, e);
    }
    #pragma unroll
    for (int o = 16; o >= H; o >>= 1)
        lmax = fmaxf(lmax, __shfl_down_sync(0xffffffffu, lmax, o));
    if (lane < H) part[wid * H + lane] = lmax;
    __syncthreads();
    if (wid == 0) {                      // full warp: shuffle-safe for any H
        float v = (lane < 8 * H) ? part[lane] : -3.4e38f;
        #pragma unroll
        for (int o = 4 * H; o >= H; o >>= 1)
            v = fmaxf(v, __shfl_down_sync(0xffffffffu, v, o));
        if (lane < H) mx_sh[lane] = v;
    }
    __syncthreads();
    float mxh = mx_sh[h];

    // Pass 2: denominator per head
    float lsum = 0.f;
    for (int i = j; i < deg; i += JJ) {
        int s = csr[start + i];
        float e = es[s * H + h] + edh;
        e = (e > 0.f) ? e : 0.2f * e;
        lsum += expf(e - mxh);
    }
    #pragma unroll
    for (int o = 16; o >= H; o >>= 1)
        lsum += __shfl_down_sync(0xffffffffu, lsum, o);
    if (lane < H) part[wid * H + lane] = lsum;
    __syncthreads();
    if (wid == 0) {
        float v = (lane < 8 * H) ? part[lane] : 0.f;
        #pragma unroll
        for (int o = 4 * H; o >= H; o >>= 1)
            v += __shfl_down_sync(0xffffffffu, v, o);
        if (lane < H) id_sh[lane] = 1.f / (v + 1e-16f);
    }
    __syncthreads();
    float idh = id_sh[h];

    // Pass 3: weighted feature accumulation, chunks of JJ edges
    float acc[F];
    #pragma unroll
    for (int k = 0; k < F; k++) acc[k] = 0.f;
    const int head = (tid * F) / C;
    for (int c0 = 0; c0 < deg; c0 += JJ) {
        int nc = min(JJ, deg - c0);
        if (j < nc) {
            int s = csr[start + c0 + j];
            if (h == 0) src_sh[j] = s;
            float e = es[s * H + h] + edh;
            e = (e > 0.f) ? e : 0.2f * e;
            alpha_sh[j * H + h] = expf(e - mxh) * idh;
        }
        __syncthreads();
        for (int jj = 0; jj < nc; jj++) {
            int s = src_sh[jj];
            float a = alpha_sh[jj * H + head];
            const float* row = xw + (size_t)s * HC + tid * F;
            if constexpr (F == 4) {
                float4 v = *reinterpret_cast<const float4*>(row);
                acc[0] = fmaf(a, v.x, acc[0]); acc[1] = fmaf(a, v.y, acc[1]);
                acc[2] = fmaf(a, v.z, acc[2]); acc[3] = fmaf(a, v.w, acc[3]);
            } else {
                float2 v = *reinterpret_cast<const float2*>(row);
                acc[0] = fmaf(a, v.x, acc[0]); acc[1] = fmaf(a, v.y, acc[1]);
            }
        }
        __syncthreads();
    }
    float* o = out + (size_t)n * HC + tid * F;
    #pragma unroll
    for (int k = 0; k < F; k++) o[k] = acc[k] + bias[tid * F + k];
}

// ---------------------------------------------------------------------------
// Fused LayerNorm + ELU; emits bf16 hi/lo splits (GEMM A operand)
// ---------------------------------------------------------------------------
__global__ __launch_bounds__(256) void ln_elu(const float* __restrict__ in,
                                              const float* __restrict__ g,
                                              const float* __restrict__ b,
                                              __nv_bfloat16* __restrict__ outH,
                                              __nv_bfloat16* __restrict__ outL) {
    int n = blockIdx.x, tid = threadIdx.x;
    const float4 v = *reinterpret_cast<const float4*>(in + (size_t)n * 1024 + tid * 4);
    float s  = v.x + v.y + v.z + v.w;
    float sq = v.x * v.x + v.y * v.y + v.z * v.z + v.w * v.w;
    __shared__ float r1[256], r2[256];
    r1[tid] = s; r2[tid] = sq; __syncthreads();
    for (int o = 128; o; o >>= 1) {
        if (tid < o) { r1[tid] += r1[tid + o]; r2[tid] += r2[tid + o]; }
        __syncthreads();
    }
    float mean = r1[0] * (1.f / 1024.f);
    float var  = r2[0] * (1.f / 1024.f) - mean * mean;
    float rstd = rsqrtf(var + 1e-5f);
    const float4 gv = *reinterpret_cast<const float4*>(g + tid * 4);
    const float4 bv = *reinterpret_cast<const float4*>(b + tid * 4);
    float xin[4] = {v.x, v.y, v.z, v.w};
    float gg[4]  = {gv.x, gv.y, gv.z, gv.w};
    float bb[4]  = {bv.x, bv.y, bv.z, bv.w};
    __nv_bfloat16 h[4], l[4];
    #pragma unroll
    for (int k = 0; k < 4; k++) {
        float y = (xin[k] - mean) * rstd * gg[k] + bb[k];
        y = (y > 0.f) ? y : expm1f(y);
        split_bf16(y, h[k], l[k]);
    }
    size_t o2 = (size_t)n * 512 + tid * 2;
    ((__nv_bfloat162*)outH)[o2]     = __nv_bfloat162(h[0], h[1]);
    ((__nv_bfloat162*)outH)[o2 + 1] = __nv_bfloat162(h[2], h[3]);
    ((__nv_bfloat162*)outL)[o2]     = __nv_bfloat162(l[0], l[1]);
    ((__nv_bfloat162*)outL)[o2 + 1] = __nv_bfloat162(l[2], l[3]);
}

// ---------------------------------------------------------------------------
// Launch
// ---------------------------------------------------------------------------
extern "C" void kernel_launch(void* const* d_in, const int* in_sizes, int n_in,
                              void* d_out, int out_size) {
    const float* x   = (const float*)d_in[0];
    const void*  ei  = d_in[1];
    const float* W1  = (const float*)d_in[2];
    const float* as1 = (const float*)d_in[3];
    const float* ad1 = (const float*)d_in[4];
    const float* b1  = (const float*)d_in[5];
    const float* g1  = (const float*)d_in[6];
    const float* bt1 = (const float*)d_in[7];
    const float* W2  = (const float*)d_in[8];
    const float* as2 = (const float*)d_in[9];
    const float* ad2 = (const float*)d_in[10];
    const float* b2  = (const float*)d_in[11];
    const float* g2  = (const float*)d_in[12];
    const float* bt2 = (const float*)d_in[13];
    const float* W3  = (const float*)d_in[14];
    const float* as3 = (const float*)d_in[15];
    const float* ad3 = (const float*)d_in[16];
    const float* b3  = (const float*)d_in[17];
    float* out = (float*)d_out;

    float *xw, *agg, *es, *ed;
    __nv_bfloat16 *ah, *al, *wh, *wl;
    int *cnt, *off, *cur, *csr;
    cudaGetSymbolAddress((void**)&xw,  d_xw);
    cudaGetSymbolAddress((void**)&agg, d_agg);
    cudaGetSymbolAddress((void**)&ah,  d_ah);
    cudaGetSymbolAddress((void**)&al,  d_al);
    cudaGetSymbolAddress((void**)&wh,  d_wh);
    cudaGetSymbolAddress((void**)&wl,  d_wl);
    cudaGetSymbolAddress((void**)&es,  d_es);
    cudaGetSymbolAddress((void**)&ed,  d_ed);
    cudaGetSymbolAddress((void**)&cnt, d_cnt);
    cudaGetSymbolAddress((void**)&off, d_off);
    cudaGetSymbolAddress((void**)&cur, d_cur);
    cudaGetSymbolAddress((void**)&csr, d_csr);

    static int attr_set = 0;
    if (!attr_set) {
        cudaFuncSetAttribute(gemm_tc, cudaFuncAttributeMaxDynamicSharedMemorySize,
                             GSM_BYTES);
        attr_set = 1;
    }

    dim3 tb(32, 8);

    detect_dtype<<<1, 1>>>((const int*)ei);
    cudaMemsetAsync(cnt, 0, NN * sizeof(int));
    count_edges<<<(ETOT + 255) / 256, 256>>>(ei, cnt);
    scan_offsets<<<1, 1024>>>(cnt, off, cur, NN);

    // ---- Layer 1 ----
    prep_x<<<(NN * DIN / 4 + 255) / 256, 256>>>(x, ah, al, (long long)NN * DIN / 4);
    prep_w<<<dim3(DIN / 32, HIDV / 32), tb>>>(W1, wh, wl, DIN, HIDV);
    gemm_tc<<<dim3((NN + 127) / 128, HIDV / 128), 256, GSM_BYTES>>>(
        ah, al, wh, wl, xw, NN, HIDV, DIN);
    scatter_edges<<<(ETOT + 255) / 256, 256>>>(ei, cur, csr);
    attn_scores<HH, C1V><<<NN, 32 * HH>>>(xw, as1, ad1, es, ed);
    gat_aggregate<HH, C1V><<<NN, 256>>>(xw, es, ed, off, csr, b1, agg);
    ln_elu<<<NN, 256>>>(agg, g1, bt1, ah, al);

    // ---- Layer 2 ----
    prep_w<<<dim3(HIDV / 32, HIDV / 32), tb>>>(W2, wh, wl, HIDV, HIDV);
    gemm_tc<<<dim3((NN + 127) / 128, HIDV / 128), 256, GSM_BYTES>>>(
        ah, al, wh, wl, xw, NN, HIDV, HIDV);
    attn_scores<HH, C1V><<<NN, 32 * HH>>>(xw, as2, ad2, es, ed);
    gat_aggregate<HH, C1V><<<NN, 256>>>(xw, es, ed, off, csr, b2, agg);
    ln_elu<<<NN, 256>>>(agg, g2, bt2, ah, al);

    // ---- Layer 3 ----
    prep_w<<<dim3(HIDV / 32, COUTV / 32), tb>>>(W3, wh, wl, HIDV, COUTV);
    gemm_tc<<<dim3((NN + 127) / 128, COUTV / 128), 256, GSM_BYTES>>>(
        ah, al, wh, wl, xw, NN, COUTV, HIDV);
    attn_scores<1, COUTV><<<NN, 32>>>(xw, as3, ad3, es, ed);
    gat_aggregate<1, COUTV><<<NN, 256>>>(xw, es, ed, off, csr, b3, out);
}